// round 9
// baseline (speedup 1.0000x reference)
#include <cuda_runtime.h>
#include <cuda_fp16.h>
#include <math.h>
#include <stdint.h>

#define S_LEN 2048
#define HID   2048
#define NH    32
#define NKV   8
#define HD    64
#define QKV_N 3072
#define CTX_N 2048
#define K_OFF 2048
#define V_OFF 2560

// scratch (no cudaMalloc allowed)
__device__ __half g_h16 [S_LEN * HID];
__device__ __half g_wq16[QKV_N * HID];
__device__ __half g_wo16[HID * CTX_N];
__device__ __half g_qkv [S_LEN * QKV_N];
__device__ __half g_ctx [S_LEN * CTX_N];

// ---------------------------------------------------------------------------
__device__ __forceinline__ unsigned sptr(const void* p) {
    return (unsigned)__cvta_generic_to_shared(p);
}
#define CP_ASYNC16(dst, src) \
    asm volatile("cp.async.cg.shared.global [%0], [%1], 16;\n" :: "r"(dst), "l"(src))
#define CP_COMMIT() asm volatile("cp.async.commit_group;\n")
#define CP_WAIT0()  asm volatile("cp.async.wait_group 0;\n")
#define CP_WAIT1()  asm volatile("cp.async.wait_group 1;\n")
#define CP_WAIT2()  asm volatile("cp.async.wait_group 2;\n")

__device__ __forceinline__ void ldm_x4(unsigned& r0, unsigned& r1, unsigned& r2, unsigned& r3,
                                       unsigned addr) {
    asm volatile("ldmatrix.sync.aligned.m8n8.x4.shared.b16 {%0,%1,%2,%3}, [%4];\n"
                 : "=r"(r0), "=r"(r1), "=r"(r2), "=r"(r3) : "r"(addr));
}
__device__ __forceinline__ void ldm_x4t(unsigned& r0, unsigned& r1, unsigned& r2, unsigned& r3,
                                        unsigned addr) {
    asm volatile("ldmatrix.sync.aligned.m8n8.x4.trans.shared.b16 {%0,%1,%2,%3}, [%4];\n"
                 : "=r"(r0), "=r"(r1), "=r"(r2), "=r"(r3) : "r"(addr));
}
__device__ __forceinline__ void mma16816(float d[4], const unsigned a[4],
                                         unsigned b0, unsigned b1) {
    asm volatile("mma.sync.aligned.m16n8k16.row.col.f32.f16.f16.f32 "
                 "{%0,%1,%2,%3}, {%4,%5,%6,%7}, {%8,%9}, {%0,%1,%2,%3};\n"
                 : "+f"(d[0]), "+f"(d[1]), "+f"(d[2]), "+f"(d[3])
                 : "r"(a[0]), "r"(a[1]), "r"(a[2]), "r"(a[3]), "r"(b0), "r"(b1));
}
__device__ __forceinline__ unsigned packh2(float x, float y) {
    __half2 h = __floats2half2_rn(x, y);
    return *reinterpret_cast<unsigned*>(&h);
}

// ---------------------------------------------------------------------------
// fp32 -> fp16 conversion, 3 segments in one launch
// ---------------------------------------------------------------------------
#define F2H_L0 (S_LEN * HID / 4)
#define F2H_L1 (QKV_N * HID / 4)
#define F2H_L2 (HID * CTX_N / 4)
#define F2H_TOT (F2H_L0 + F2H_L1 + F2H_L2)

__global__ __launch_bounds__(256) void f2h3(const float4* __restrict__ s0, __half2* __restrict__ d0,
                                            const float4* __restrict__ s1, __half2* __restrict__ d1,
                                            const float4* __restrict__ s2, __half2* __restrict__ d2) {
    int i = blockIdx.x * 256 + threadIdx.x;
    const float4* s;
    __half2* d;
    if (i < F2H_L0) { s = s0; d = d0; }
    else if (i < F2H_L0 + F2H_L1) { i -= F2H_L0; s = s1; d = d1; }
    else if (i < F2H_TOT) { i -= F2H_L0 + F2H_L1; s = s2; d = d2; }
    else return;
    const float4 v = s[i];
    d[2 * i]     = __floats2half2_rn(v.x, v.y);
    d[2 * i + 1] = __floats2half2_rn(v.z, v.w);
}

// ---------------------------------------------------------------------------
// C[m][n] = sum_k A[m][k]*B[n][k], fp16 in / fp32 acc.  128 x NT x 32 tiles,
// 256 thr = 8 warps (2m x 4n, warp tile 64 x NT/4), 4-stage cp.async pipeline.
// smem per stage: A[128][32] + B[NT][32], chunk swizzle c^((r>>1)&3).
// ---------------------------------------------------------------------------
#define GNS 4
#define GA_H (128 * 32)

template <int NT, bool HALF_OUT>
__global__ __launch_bounds__(256, 2) void gemm_tn_h(const __half* __restrict__ A,
                                                    const __half* __restrict__ B,
                                                    void* __restrict__ Cv,
                                                    int M, int N, int K) {
    constexpr int GB_H = NT * 32;          // B halves per stage
    constexpr int STG = GA_H + GB_H;       // stage halves
    constexpr int NTL = NT / 32;           // n8-tiles per warp
    extern __shared__ __half gsm[];
    const int tid  = threadIdx.x;
    const int warp = tid >> 5, lane = tid & 31;
    const int gid  = lane >> 2, tg = lane & 3;
    const int wm   = warp & 1,  wn = warp >> 1;
    const int m0 = blockIdx.y * 128, n0 = blockIdx.x * NT;

    // A loader: 512 chunks (2/thread); B loader: NT*4 chunks (NT/64 per thread)
    int swa[2]; long ga[2];
#pragma unroll
    for (int i = 0; i < 2; i++) {
        const int f = tid + i * 256, r = f >> 2, c = f & 3;
        swa[i] = r * 32 + ((c ^ ((r >> 1) & 3)) << 3);
        ga[i]  = (long)(m0 + r) * K + c * 8;
    }
    int swb[NT / 64]; long gb[NT / 64];
#pragma unroll
    for (int i = 0; i < NT / 64; i++) {
        const int f = tid + i * 256, r = f >> 2, c = f & 3;
        swb[i] = r * 32 + ((c ^ ((r >> 1) & 3)) << 3);
        gb[i]  = (long)(n0 + r) * K + c * 8;
    }

    float acc[4][NTL][4] = {};

#define G_LOAD(IT)                                                      \
    do {                                                                \
        const int kk_ = (IT) << 5;                                      \
        __half* a_ = gsm + ((IT) & (GNS - 1)) * STG;                    \
        __half* b_ = a_ + GA_H;                                         \
        _Pragma("unroll")                                               \
        for (int i_ = 0; i_ < 2; i_++)                                  \
            CP_ASYNC16(sptr(a_ + swa[i_]), A + ga[i_] + kk_);           \
        _Pragma("unroll")                                               \
        for (int i_ = 0; i_ < NT / 64; i_++)                            \
            CP_ASYNC16(sptr(b_ + swb[i_]), B + gb[i_] + kk_);           \
        CP_COMMIT();                                                    \
    } while (0)

    const int nIter = K >> 5;
    G_LOAD(0); G_LOAD(1); G_LOAD(2);

    for (int it = 0; it < nIter; ++it) {
        if (it + 3 <= nIter)      { CP_WAIT2(); }
        else if (it + 2 == nIter) { CP_WAIT1(); }
        else                      { CP_WAIT0(); }
        __syncthreads();
        if (it + 3 < nIter) G_LOAD(it + 3);

        const __half* a = gsm + (it & (GNS - 1)) * STG;
        const __half* b = a + GA_H;

        unsigned bf[NTL][4];
        {
            const int rb = wn * (NT / 4) + (lane & 7);
            const int cb = lane >> 3;
#pragma unroll
            for (int nt = 0; nt < NTL; nt++) {
                const int r = rb + nt * 8;
                ldm_x4(bf[nt][0], bf[nt][1], bf[nt][2], bf[nt][3],
                       sptr(b + r * 32 + ((cb ^ ((r >> 1) & 3)) << 3)));
            }
        }
#pragma unroll
        for (int p = 0; p < 2; p++) {
            unsigned af[4][4];
            const int ra = wm * 64 + (lane & 7) + ((lane >> 3) & 1) * 8;
            const int ca = p * 2 + ((lane >> 4) & 1);
#pragma unroll
            for (int mt = 0; mt < 4; mt++) {
                const int r = ra + mt * 16;
                ldm_x4(af[mt][0], af[mt][1], af[mt][2], af[mt][3],
                       sptr(a + r * 32 + ((ca ^ ((r >> 1) & 3)) << 3)));
            }
#pragma unroll
            for (int nt = 0; nt < NTL; nt++)
#pragma unroll
                for (int mt = 0; mt < 4; mt++)
                    mma16816(acc[mt][nt], af[mt], bf[nt][2 * p], bf[nt][2 * p + 1]);
        }
    }

#pragma unroll
    for (int mt = 0; mt < 4; mt++)
#pragma unroll
        for (int nt = 0; nt < NTL; nt++) {
            const int r = m0 + wm * 64 + mt * 16 + gid;
            const int c = n0 + wn * (NT / 4) + nt * 8 + tg * 2;
            if (HALF_OUT) {
                __half* C = (__half*)Cv;
                *(__half2*)&C[(long)r * N + c] =
                    __floats2half2_rn(acc[mt][nt][0], acc[mt][nt][1]);
                *(__half2*)&C[(long)(r + 8) * N + c] =
                    __floats2half2_rn(acc[mt][nt][2], acc[mt][nt][3]);
            } else {
                float* C = (float*)Cv;
                *(float2*)&C[(long)r * N + c] = make_float2(acc[mt][nt][0], acc[mt][nt][1]);
                *(float2*)&C[(long)(r + 8) * N + c] = make_float2(acc[mt][nt][2], acc[mt][nt][3]);
            }
        }
}

#define GEMM_SMEM_Q (GNS * (GA_H + 64 * 32) * 2)    // NT=64
#define GEMM_SMEM_O (GNS * (GA_H + 128 * 32) * 2)   // NT=128

// ---------------------------------------------------------------------------
// RoPE (neox) in-place on fp16 q,k.  positions = arange(S).
// Folds 0.125 * log2(e) into q (FA softmax runs in exp2 domain).
// 256 threads = 8 heads per block.
// ---------------------------------------------------------------------------
__global__ __launch_bounds__(256) void rope_h(__half* __restrict__ qkv) {
    const int s  = blockIdx.x;
    const int hh = blockIdx.y * 8 + (threadIdx.x >> 5);
    const int i  = threadIdx.x & 31;
    const int base = (hh < NH) ? hh * HD : (K_OFF + (hh - NH) * HD);
    const float qs = (hh < NH) ? 0.125f * 1.44269504f : 1.0f;
    const float inv = powf(10000.0f, -(2.0f * (float)i) / 64.0f);
    const float ang = (float)s * inv;
    const float c = cosf(ang), sn = sinf(ang);
    __half* row = qkv + (long)s * QKV_N + base;
    const float x1 = __half2float(row[i]);
    const float x2 = __half2float(row[i + 32]);
    row[i]      = __float2half_rn((x1 * c - x2 * sn) * qs);
    row[i + 32] = __float2half_rn((x2 * c + x1 * sn) * qs);
}

// ---------------------------------------------------------------------------
// Causal flash attention, fp16 mma.  128 q-rows/block, 8 warps (16 rows each),
// 3-stage K/V cp.async pipeline, V via ldmatrix.x4.trans, P stays in regs.
// Softmax in exp2 domain (log2e folded into q at rope time).
// ---------------------------------------------------------------------------
#define FQ_H (128 * 64)
#define FKV_H (64 * 64)
#define FA_SMEM ((FQ_H + 3 * 2 * FKV_H) * 2)

__global__ __launch_bounds__(256, 2) void flash_attn_h(const __half* __restrict__ qkv,
                                                       __half* __restrict__ ctx) {
    extern __shared__ __half fsm[];
    __half* Qs = fsm;   // [128][64]

    const int qt  = (S_LEN / 128 - 1) - blockIdx.x;   // longest tiles first
    const int h   = blockIdx.y;
    const int kvh = h >> 2;
    const int tid = threadIdx.x, warp = tid >> 5, lane = tid & 31;
    const int gid = lane >> 2, tg = lane & 3;
    const int q0 = qt * 128, woff = warp * 16;
    const int jmax = (q0 + 127) >> 6;

    int rr[2], cc8[2], sw[2];
#pragma unroll
    for (int i = 0; i < 2; i++) {
        const int f = tid + i * 256;
        const int r = f >> 3, c = f & 7;
        rr[i] = r; cc8[i] = c * 8;
        sw[i] = r * 64 + ((c ^ (r & 7)) << 3);
    }

#define FA_LOADKV(J)                                                                     \
    do {                                                                                 \
        const int kb_ = (J) * 64;                                                        \
        __half* kd_ = fsm + FQ_H + ((J) % 3) * 2 * FKV_H;                                \
        __half* vd_ = kd_ + FKV_H;                                                       \
        _Pragma("unroll")                                                                \
        for (int i_ = 0; i_ < 2; i_++) {                                                 \
            CP_ASYNC16(sptr(kd_ + sw[i_]),                                               \
                       qkv + (long)(kb_ + rr[i_]) * QKV_N + K_OFF + kvh * HD + cc8[i_]); \
            CP_ASYNC16(sptr(vd_ + sw[i_]),                                               \
                       qkv + (long)(kb_ + rr[i_]) * QKV_N + V_OFF + kvh * HD + cc8[i_]); \
        }                                                                                \
        CP_COMMIT();                                                                     \
    } while (0)

    // prologue: Q (1024 chunks, 4/thread) then KV0, KV1
#pragma unroll
    for (int i = 0; i < 4; i++) {
        const int f = tid + i * 256;
        const int r = f >> 3, c = f & 7;
        CP_ASYNC16(sptr(Qs + r * 64 + ((c ^ (r & 7)) << 3)),
                   qkv + (long)(q0 + r) * QKV_N + h * HD + c * 8);
    }
    CP_COMMIT();
    FA_LOADKV(0);
    FA_LOADKV(1);

    CP_WAIT2();          // Q done (KV0, KV1 may be in flight)
    __syncthreads();

    unsigned qa[4][4];
    {
        const int r = woff + (lane & 7) + ((lane >> 3) & 1) * 8;
        const int cb = (lane >> 4) & 1;
#pragma unroll
        for (int ks = 0; ks < 4; ks++) {
            const int c = 2 * ks + cb;
            ldm_x4(qa[ks][0], qa[ks][1], qa[ks][2], qa[ks][3],
                   sptr(Qs + r * 64 + ((c ^ (r & 7)) << 3)));
        }
    }

    float acc[8][4] = {};
    float m0r = -INFINITY, m1r = -INFINITY, l0r = 0.0f, l1r = 0.0f;

    for (int j = 0; j <= jmax; ++j) {
        if (j < jmax) { CP_WAIT1(); } else { CP_WAIT0(); }
        __syncthreads();
        if (j + 2 <= jmax) FA_LOADKV(j + 2);

        // skip fully-masked iterations for this warp (still did sync+prefetch)
        if ((j << 6) > q0 + woff + 15) continue;

        const __half* ksm = fsm + FQ_H + (j % 3) * 2 * FKV_H;
        const __half* vsm = ksm + FKV_H;

        // ---- S = Q K^T ----
        float sf[8][4] = {};
#pragma unroll
        for (int p = 0; p < 2; p++) {
            const int rb = lane & 7;
            const int cb = 4 * p + (lane >> 3);
#pragma unroll
            for (int nt = 0; nt < 8; nt++) {
                unsigned kb[4];
                const int r = nt * 8 + rb;
                ldm_x4(kb[0], kb[1], kb[2], kb[3],
                       sptr(ksm + r * 64 + ((cb ^ (r & 7)) << 3)));
                mma16816(sf[nt], qa[2 * p],     kb[0], kb[1]);
                mma16816(sf[nt], qa[2 * p + 1], kb[2], kb[3]);
            }
        }

        // ---- causal mask (absolute coords; only near diagonal) ----
        if ((j << 6) + 63 > q0 + woff) {
            const int r0m = q0 + woff + gid;
            const int r1m = r0m + 8;
#pragma unroll
            for (int nt = 0; nt < 8; nt++) {
                const int c0 = (j << 6) + nt * 8 + tg * 2;
                if (c0 > r0m)     sf[nt][0] = -INFINITY;
                if (c0 + 1 > r0m) sf[nt][1] = -INFINITY;
                if (c0 > r1m)     sf[nt][2] = -INFINITY;
                if (c0 + 1 > r1m) sf[nt][3] = -INFINITY;
            }
        }

        // ---- online softmax (exp2 domain) ----
        float mx0 = sf[0][0], mx1 = sf[0][2];
#pragma unroll
        for (int nt = 0; nt < 8; nt++) {
            mx0 = fmaxf(mx0, fmaxf(sf[nt][0], sf[nt][1]));
            mx1 = fmaxf(mx1, fmaxf(sf[nt][2], sf[nt][3]));
        }
        mx0 = fmaxf(mx0, __shfl_xor_sync(0xffffffffu, mx0, 1));
        mx0 = fmaxf(mx0, __shfl_xor_sync(0xffffffffu, mx0, 2));
        mx1 = fmaxf(mx1, __shfl_xor_sync(0xffffffffu, mx1, 1));
        mx1 = fmaxf(mx1, __shfl_xor_sync(0xffffffffu, mx1, 2));
        const float mn0 = fmaxf(m0r, mx0);
        const float mn1 = fmaxf(m1r, mx1);
        const float al0 = exp2f(m0r - mn0);
        const float al1 = exp2f(m1r - mn1);
        m0r = mn0; m1r = mn1;
        float s0 = 0.0f, s1 = 0.0f;
#pragma unroll
        for (int nt = 0; nt < 8; nt++) {
            sf[nt][0] = exp2f(sf[nt][0] - mn0);
            sf[nt][1] = exp2f(sf[nt][1] - mn0);
            sf[nt][2] = exp2f(sf[nt][2] - mn1);
            sf[nt][3] = exp2f(sf[nt][3] - mn1);
            s0 += sf[nt][0] + sf[nt][1];
            s1 += sf[nt][2] + sf[nt][3];
        }
        s0 += __shfl_xor_sync(0xffffffffu, s0, 1);
        s0 += __shfl_xor_sync(0xffffffffu, s0, 2);
        s1 += __shfl_xor_sync(0xffffffffu, s1, 1);
        s1 += __shfl_xor_sync(0xffffffffu, s1, 2);
        l0r = l0r * al0 + s0;
        l1r = l1r * al1 + s1;
#pragma unroll
        for (int dt = 0; dt < 8; dt++) {
            acc[dt][0] *= al0; acc[dt][1] *= al0;
            acc[dt][2] *= al1; acc[dt][3] *= al1;
        }

        // ---- P: C-frag -> A-frag repack (registers only) ----
        unsigned pa[4][4];
#pragma unroll
        for (int ks = 0; ks < 4; ks++) {
            pa[ks][0] = packh2(sf[2 * ks][0],     sf[2 * ks][1]);
            pa[ks][1] = packh2(sf[2 * ks][2],     sf[2 * ks][3]);
            pa[ks][2] = packh2(sf[2 * ks + 1][0], sf[2 * ks + 1][1]);
            pa[ks][3] = packh2(sf[2 * ks + 1][2], sf[2 * ks + 1][3]);
        }

        // ---- O += P V  (V via ldmatrix.trans) ----
#pragma unroll
        for (int p = 0; p < 2; p++) {
            const int r = 32 * p + (lane & 7) + (lane >> 3) * 8;
#pragma unroll
            for (int dt = 0; dt < 8; dt++) {
                unsigned vb[4];
                ldm_x4t(vb[0], vb[1], vb[2], vb[3],
                        sptr(vsm + r * 64 + ((dt ^ (r & 7)) << 3)));
                mma16816(acc[dt], pa[2 * p],     vb[0], vb[1]);
                mma16816(acc[dt], pa[2 * p + 1], vb[2], vb[3]);
            }
        }
    }

    // ---- epilogue ----
    const float il0 = 1.0f / l0r;
    const float il1 = 1.0f / l1r;
#pragma unroll
    for (int dt = 0; dt < 8; dt++) {
        const int r = q0 + woff + gid;
        const int c = h * HD + dt * 8 + tg * 2;
        *(__half2*)&ctx[(long)r * CTX_N + c] =
            __floats2half2_rn(acc[dt][0] * il0, acc[dt][1] * il0);
        *(__half2*)&ctx[(long)(r + 8) * CTX_N + c] =
            __floats2half2_rn(acc[dt][2] * il1, acc[dt][3] * il1);
    }
}

// ---------------------------------------------------------------------------
extern "C" void kernel_launch(void* const* d_in, const int* in_sizes, int n_in,
                              void* d_out, int out_size) {
    const float* hidden = (const float*)d_in[1];
    const float* w_qkv  = (const float*)d_in[2];
    const float* w_o    = (const float*)d_in[3];
    float* out = (float*)d_out;

    __half *h16, *wq16, *wo16, *qkv, *ctx;
    cudaGetSymbolAddress((void**)&h16,  g_h16);
    cudaGetSymbolAddress((void**)&wq16, g_wq16);
    cudaGetSymbolAddress((void**)&wo16, g_wo16);
    cudaGetSymbolAddress((void**)&qkv,  g_qkv);
    cudaGetSymbolAddress((void**)&ctx,  g_ctx);

    cudaFuncSetAttribute(gemm_tn_h<64, true>,   cudaFuncAttributeMaxDynamicSharedMemorySize, GEMM_SMEM_Q);
    cudaFuncSetAttribute(gemm_tn_h<128, false>, cudaFuncAttributeMaxDynamicSharedMemorySize, GEMM_SMEM_O);
    cudaFuncSetAttribute(flash_attn_h,          cudaFuncAttributeMaxDynamicSharedMemorySize, FA_SMEM);

    // 0) fp32 -> fp16 conversions (single launch, 3 segments)
    f2h3<<<(F2H_TOT + 255) / 256, 256>>>((const float4*)hidden, (__half2*)h16,
                                         (const float4*)w_qkv, (__half2*)wq16,
                                         (const float4*)w_o,   (__half2*)wo16);

    // 1) fused QKV projection -> fp16 (128x64 tiles vs wave quantization)
    gemm_tn_h<64, true><<<dim3(QKV_N / 64, S_LEN / 128), 256, GEMM_SMEM_Q>>>(h16, wq16, qkv, S_LEN, QKV_N, HID);
    // 2) RoPE (0.125*log2e folded into q)
    rope_h<<<dim3(S_LEN, 5), 256>>>(qkv);
    // 3) causal flash attention (GQA)
    flash_attn_h<<<dim3(S_LEN / 128, NH), 256, FA_SMEM>>>(qkv, ctx);
    // 4) output projection -> fp32 (single wave at 128x128)
    gemm_tn_h<128, false><<<dim3(CTX_N / 128, S_LEN / 128), 256, GEMM_SMEM_O>>>(ctx, wo16, out, S_LEN, CTX_N, CTX_N);
}

// round 10
// speedup vs baseline: 1.1024x; 1.1024x over previous
#include <cuda_runtime.h>
#include <cuda_fp16.h>
#include <math.h>
#include <stdint.h>

#define S_LEN 2048
#define HID   2048
#define NH    32
#define NKV   8
#define HD    64
#define QKV_N 3072
#define CTX_N 2048
#define K_OFF 2048
#define V_OFF 2560

// scratch (no cudaMalloc allowed)
__device__ __half g_h16 [S_LEN * HID];
__device__ __half g_wq16[QKV_N * HID];
__device__ __half g_wo16[HID * CTX_N];
__device__ __half g_qkv [S_LEN * QKV_N];
__device__ __half g_ctx [S_LEN * CTX_N];

// ---------------------------------------------------------------------------
__device__ __forceinline__ unsigned sptr(const void* p) {
    return (unsigned)__cvta_generic_to_shared(p);
}
#define CP_ASYNC16(dst, src) \
    asm volatile("cp.async.cg.shared.global [%0], [%1], 16;\n" :: "r"(dst), "l"(src))
#define CP_COMMIT() asm volatile("cp.async.commit_group;\n")
#define CP_WAIT0()  asm volatile("cp.async.wait_group 0;\n")
#define CP_WAIT1()  asm volatile("cp.async.wait_group 1;\n")
#define CP_WAIT2()  asm volatile("cp.async.wait_group 2;\n")

__device__ __forceinline__ void ldm_x4(unsigned& r0, unsigned& r1, unsigned& r2, unsigned& r3,
                                       unsigned addr) {
    asm volatile("ldmatrix.sync.aligned.m8n8.x4.shared.b16 {%0,%1,%2,%3}, [%4];\n"
                 : "=r"(r0), "=r"(r1), "=r"(r2), "=r"(r3) : "r"(addr));
}
__device__ __forceinline__ void ldm_x4t(unsigned& r0, unsigned& r1, unsigned& r2, unsigned& r3,
                                        unsigned addr) {
    asm volatile("ldmatrix.sync.aligned.m8n8.x4.trans.shared.b16 {%0,%1,%2,%3}, [%4];\n"
                 : "=r"(r0), "=r"(r1), "=r"(r2), "=r"(r3) : "r"(addr));
}
__device__ __forceinline__ void mma16816(float d[4], const unsigned a[4],
                                         unsigned b0, unsigned b1) {
    asm volatile("mma.sync.aligned.m16n8k16.row.col.f32.f16.f16.f32 "
                 "{%0,%1,%2,%3}, {%4,%5,%6,%7}, {%8,%9}, {%0,%1,%2,%3};\n"
                 : "+f"(d[0]), "+f"(d[1]), "+f"(d[2]), "+f"(d[3])
                 : "r"(a[0]), "r"(a[1]), "r"(a[2]), "r"(a[3]), "r"(b0), "r"(b1));
}
__device__ __forceinline__ unsigned packh2(float x, float y) {
    __half2 h = __floats2half2_rn(x, y);
    return *reinterpret_cast<unsigned*>(&h);
}

// ---------------------------------------------------------------------------
// fp32 -> fp16 conversion, 3 segments in one launch
// ---------------------------------------------------------------------------
#define F2H_L0 (S_LEN * HID / 4)
#define F2H_L1 (QKV_N * HID / 4)
#define F2H_L2 (HID * CTX_N / 4)
#define F2H_TOT (F2H_L0 + F2H_L1 + F2H_L2)

__global__ __launch_bounds__(256) void f2h3(const float4* __restrict__ s0, __half2* __restrict__ d0,
                                            const float4* __restrict__ s1, __half2* __restrict__ d1,
                                            const float4* __restrict__ s2, __half2* __restrict__ d2) {
    int i = blockIdx.x * 256 + threadIdx.x;
    const float4* s;
    __half2* d;
    if (i < F2H_L0) { s = s0; d = d0; }
    else if (i < F2H_L0 + F2H_L1) { i -= F2H_L0; s = s1; d = d1; }
    else if (i < F2H_TOT) { i -= F2H_L0 + F2H_L1; s = s2; d = d2; }
    else return;
    const float4 v = s[i];
    d[2 * i]     = __floats2half2_rn(v.x, v.y);
    d[2 * i + 1] = __floats2half2_rn(v.z, v.w);
}

// ---------------------------------------------------------------------------
// C[m][n] = sum_k A[m][k]*B[n][k], fp16 in / fp32 acc.  128 x NT x 32 tiles,
// 256 thr = 8 warps (2m x 4n, warp tile 64 x NT/4), 4-stage cp.async pipeline.
// smem per stage: A[128][32] + B[NT][32], chunk swizzle c^((r>>1)&3).
// ---------------------------------------------------------------------------
#define GNS 4
#define GA_H (128 * 32)

template <int NT, bool HALF_OUT>
__global__ __launch_bounds__(256, 2) void gemm_tn_h(const __half* __restrict__ A,
                                                    const __half* __restrict__ B,
                                                    void* __restrict__ Cv,
                                                    int M, int N, int K) {
    constexpr int GB_H = NT * 32;          // B halves per stage
    constexpr int STG = GA_H + GB_H;       // stage halves
    constexpr int NTL = NT / 32;           // n8-tiles per warp
    constexpr int NBCH = NT * 4;           // B 16B-chunks per stage
    extern __shared__ __half gsm[];
    const int tid  = threadIdx.x;
    const int warp = tid >> 5, lane = tid & 31;
    const int gid  = lane >> 2, tg = lane & 3;
    const int wm   = warp & 1,  wn = warp >> 1;
    const int m0 = blockIdx.y * 128, n0 = blockIdx.x * NT;

    // A loader: 512 chunks (2/thread); B loader: NBCH chunks (guarded)
    int swa[2]; long ga[2];
#pragma unroll
    for (int i = 0; i < 2; i++) {
        const int f = tid + i * 256, r = f >> 2, c = f & 3;
        swa[i] = r * 32 + ((c ^ ((r >> 1) & 3)) << 3);
        ga[i]  = (long)(m0 + r) * K + c * 8;
    }
    int swb[2]; long gb[2];
#pragma unroll
    for (int i = 0; i < 2; i++) {
        const int f = tid + i * 256;
        const int r = (f < NBCH) ? (f >> 2) : 0;
        const int c = f & 3;
        swb[i] = r * 32 + ((c ^ ((r >> 1) & 3)) << 3);
        gb[i]  = (long)(n0 + r) * K + c * 8;
    }

    float acc[4][NTL][4] = {};

#define G_LOAD(IT)                                                      \
    do {                                                                \
        const int kk_ = (IT) << 5;                                      \
        __half* a_ = gsm + ((IT) & (GNS - 1)) * STG;                    \
        __half* b_ = a_ + GA_H;                                         \
        _Pragma("unroll")                                               \
        for (int i_ = 0; i_ < 2; i_++)                                  \
            CP_ASYNC16(sptr(a_ + swa[i_]), A + ga[i_] + kk_);           \
        _Pragma("unroll")                                               \
        for (int i_ = 0; i_ < 2; i_++)                                  \
            if (tid + i_ * 256 < NBCH)                                  \
                CP_ASYNC16(sptr(b_ + swb[i_]), B + gb[i_] + kk_);       \
        CP_COMMIT();                                                    \
    } while (0)

    const int nIter = K >> 5;
    G_LOAD(0); G_LOAD(1); G_LOAD(2);

    for (int it = 0; it < nIter; ++it) {
        if (it + 3 <= nIter)      { CP_WAIT2(); }
        else if (it + 2 == nIter) { CP_WAIT1(); }
        else                      { CP_WAIT0(); }
        __syncthreads();
        if (it + 3 < nIter) G_LOAD(it + 3);

        const __half* a = gsm + (it & (GNS - 1)) * STG;
        const __half* b = a + GA_H;

        unsigned bf[NTL][4];
        {
            const int rb = wn * (NT / 4) + (lane & 7);
            const int cb = lane >> 3;
#pragma unroll
            for (int nt = 0; nt < NTL; nt++) {
                const int r = rb + nt * 8;
                ldm_x4(bf[nt][0], bf[nt][1], bf[nt][2], bf[nt][3],
                       sptr(b + r * 32 + ((cb ^ ((r >> 1) & 3)) << 3)));
            }
        }
#pragma unroll
        for (int p = 0; p < 2; p++) {
            unsigned af[4][4];
            const int ra = wm * 64 + (lane & 7) + ((lane >> 3) & 1) * 8;
            const int ca = p * 2 + ((lane >> 4) & 1);
#pragma unroll
            for (int mt = 0; mt < 4; mt++) {
                const int r = ra + mt * 16;
                ldm_x4(af[mt][0], af[mt][1], af[mt][2], af[mt][3],
                       sptr(a + r * 32 + ((ca ^ ((r >> 1) & 3)) << 3)));
            }
#pragma unroll
            for (int nt = 0; nt < NTL; nt++)
#pragma unroll
                for (int mt = 0; mt < 4; mt++)
                    mma16816(acc[mt][nt], af[mt], bf[nt][2 * p], bf[nt][2 * p + 1]);
        }
    }

#pragma unroll
    for (int mt = 0; mt < 4; mt++)
#pragma unroll
        for (int nt = 0; nt < NTL; nt++) {
            const int r = m0 + wm * 64 + mt * 16 + gid;
            const int c = n0 + wn * (NT / 4) + nt * 8 + tg * 2;
            if (HALF_OUT) {
                __half* C = (__half*)Cv;
                *(__half2*)&C[(long)r * N + c] =
                    __floats2half2_rn(acc[mt][nt][0], acc[mt][nt][1]);
                *(__half2*)&C[(long)(r + 8) * N + c] =
                    __floats2half2_rn(acc[mt][nt][2], acc[mt][nt][3]);
            } else {
                float* C = (float*)Cv;
                *(float2*)&C[(long)r * N + c] = make_float2(acc[mt][nt][0], acc[mt][nt][1]);
                *(float2*)&C[(long)(r + 8) * N + c] = make_float2(acc[mt][nt][2], acc[mt][nt][3]);
            }
        }
}

#define GEMM_SMEM_Q (GNS * (GA_H + 96 * 32) * 2)    // NT=96
#define GEMM_SMEM_O (GNS * (GA_H + 128 * 32) * 2)   // NT=128

// ---------------------------------------------------------------------------
// RoPE (neox) in-place on fp16 q,k.  positions = arange(S).
// Folds 0.125 * log2(e) into q (FA softmax runs in exp2 domain).
// 256 threads = 8 heads per block.
// ---------------------------------------------------------------------------
__global__ __launch_bounds__(256) void rope_h(__half* __restrict__ qkv) {
    const int s  = blockIdx.x;
    const int hh = blockIdx.y * 8 + (threadIdx.x >> 5);
    const int i  = threadIdx.x & 31;
    const int base = (hh < NH) ? hh * HD : (K_OFF + (hh - NH) * HD);
    const float qs = (hh < NH) ? 0.125f * 1.44269504f : 1.0f;
    const float inv = powf(10000.0f, -(2.0f * (float)i) / 64.0f);
    const float ang = (float)s * inv;
    const float c = cosf(ang), sn = sinf(ang);
    __half* row = qkv + (long)s * QKV_N + base;
    const float x1 = __half2float(row[i]);
    const float x2 = __half2float(row[i + 32]);
    row[i]      = __float2half_rn((x1 * c - x2 * sn) * qs);
    row[i + 32] = __float2half_rn((x2 * c + x1 * sn) * qs);
}

// ---------------------------------------------------------------------------
// Causal flash attention, fp16 mma.  128 q-rows/block, 8 warps (16 rows each),
// 3-stage K/V cp.async pipeline, V via ldmatrix.x4.trans, P stays in regs.
// Softmax in exp2 domain; row sums via MMA against all-ones B fragment.
// ---------------------------------------------------------------------------
#define FQ_H (128 * 64)
#define FKV_H (64 * 64)
#define FA_SMEM ((FQ_H + 3 * 2 * FKV_H) * 2)
#define ONES_H2 0x3C003C00u

__global__ __launch_bounds__(256, 2) void flash_attn_h(const __half* __restrict__ qkv,
                                                       __half* __restrict__ ctx) {
    extern __shared__ __half fsm[];
    __half* Qs = fsm;   // [128][64]

    const int qt  = (S_LEN / 128 - 1) - blockIdx.x;   // longest tiles first
    const int h   = blockIdx.y;
    const int kvh = h >> 2;
    const int tid = threadIdx.x, warp = tid >> 5, lane = tid & 31;
    const int gid = lane >> 2, tg = lane & 3;
    const int q0 = qt * 128, woff = warp * 16;
    const int jmax = (q0 + 127) >> 6;

    int rr[2], cc8[2], sw[2];
#pragma unroll
    for (int i = 0; i < 2; i++) {
        const int f = tid + i * 256;
        const int r = f >> 3, c = f & 7;
        rr[i] = r; cc8[i] = c * 8;
        sw[i] = r * 64 + ((c ^ (r & 7)) << 3);
    }

#define FA_LOADKV(J)                                                                     \
    do {                                                                                 \
        const int kb_ = (J) * 64;                                                        \
        __half* kd_ = fsm + FQ_H + ((J) % 3) * 2 * FKV_H;                                \
        __half* vd_ = kd_ + FKV_H;                                                       \
        _Pragma("unroll")                                                                \
        for (int i_ = 0; i_ < 2; i_++) {                                                 \
            CP_ASYNC16(sptr(kd_ + sw[i_]),                                               \
                       qkv + (long)(kb_ + rr[i_]) * QKV_N + K_OFF + kvh * HD + cc8[i_]); \
            CP_ASYNC16(sptr(vd_ + sw[i_]),                                               \
                       qkv + (long)(kb_ + rr[i_]) * QKV_N + V_OFF + kvh * HD + cc8[i_]); \
        }                                                                                \
        CP_COMMIT();                                                                     \
    } while (0)

    // prologue: Q (1024 chunks, 4/thread) then KV0, KV1
#pragma unroll
    for (int i = 0; i < 4; i++) {
        const int f = tid + i * 256;
        const int r = f >> 3, c = f & 7;
        CP_ASYNC16(sptr(Qs + r * 64 + ((c ^ (r & 7)) << 3)),
                   qkv + (long)(q0 + r) * QKV_N + h * HD + c * 8);
    }
    CP_COMMIT();
    FA_LOADKV(0);
    FA_LOADKV(1);

    CP_WAIT2();          // Q done (KV0, KV1 may be in flight)
    __syncthreads();

    unsigned qa[4][4];
    {
        const int r = woff + (lane & 7) + ((lane >> 3) & 1) * 8;
        const int cb = (lane >> 4) & 1;
#pragma unroll
        for (int ks = 0; ks < 4; ks++) {
            const int c = 2 * ks + cb;
            ldm_x4(qa[ks][0], qa[ks][1], qa[ks][2], qa[ks][3],
                   sptr(Qs + r * 64 + ((c ^ (r & 7)) << 3)));
        }
    }

    float acc[8][4] = {};
    float lsum[4] = {};
    float m0r = -INFINITY, m1r = -INFINITY;

    for (int j = 0; j <= jmax; ++j) {
        if (j < jmax) { CP_WAIT1(); } else { CP_WAIT0(); }
        __syncthreads();
        if (j + 2 <= jmax) FA_LOADKV(j + 2);

        // skip fully-masked iterations for this warp (still did sync+prefetch)
        if ((j << 6) > q0 + woff + 15) continue;

        const __half* ksm = fsm + FQ_H + (j % 3) * 2 * FKV_H;
        const __half* vsm = ksm + FKV_H;

        // ---- S = Q K^T ----
        float sf[8][4] = {};
#pragma unroll
        for (int p = 0; p < 2; p++) {
            const int rb = lane & 7;
            const int cb = 4 * p + (lane >> 3);
#pragma unroll
            for (int nt = 0; nt < 8; nt++) {
                unsigned kb[4];
                const int r = nt * 8 + rb;
                ldm_x4(kb[0], kb[1], kb[2], kb[3],
                       sptr(ksm + r * 64 + ((cb ^ (r & 7)) << 3)));
                mma16816(sf[nt], qa[2 * p],     kb[0], kb[1]);
                mma16816(sf[nt], qa[2 * p + 1], kb[2], kb[3]);
            }
        }

        // ---- causal mask (absolute coords; only near diagonal) ----
        if ((j << 6) + 63 > q0 + woff) {
            const int r0m = q0 + woff + gid;
            const int r1m = r0m + 8;
#pragma unroll
            for (int nt = 0; nt < 8; nt++) {
                const int c0 = (j << 6) + nt * 8 + tg * 2;
                if (c0 > r0m)     sf[nt][0] = -INFINITY;
                if (c0 + 1 > r0m) sf[nt][1] = -INFINITY;
                if (c0 > r1m)     sf[nt][2] = -INFINITY;
                if (c0 + 1 > r1m) sf[nt][3] = -INFINITY;
            }
        }

        // ---- online softmax (exp2 domain; sums via MMA below) ----
        float mx0 = sf[0][0], mx1 = sf[0][2];
#pragma unroll
        for (int nt = 0; nt < 8; nt++) {
            mx0 = fmaxf(mx0, fmaxf(sf[nt][0], sf[nt][1]));
            mx1 = fmaxf(mx1, fmaxf(sf[nt][2], sf[nt][3]));
        }
        mx0 = fmaxf(mx0, __shfl_xor_sync(0xffffffffu, mx0, 1));
        mx0 = fmaxf(mx0, __shfl_xor_sync(0xffffffffu, mx0, 2));
        mx1 = fmaxf(mx1, __shfl_xor_sync(0xffffffffu, mx1, 1));
        mx1 = fmaxf(mx1, __shfl_xor_sync(0xffffffffu, mx1, 2));
        const float mn0 = fmaxf(m0r, mx0);
        const float mn1 = fmaxf(m1r, mx1);
        const float al0 = exp2f(m0r - mn0);
        const float al1 = exp2f(m1r - mn1);
        m0r = mn0; m1r = mn1;
#pragma unroll
        for (int nt = 0; nt < 8; nt++) {
            sf[nt][0] = exp2f(sf[nt][0] - mn0);
            sf[nt][1] = exp2f(sf[nt][1] - mn0);
            sf[nt][2] = exp2f(sf[nt][2] - mn1);
            sf[nt][3] = exp2f(sf[nt][3] - mn1);
        }
#pragma unroll
        for (int dt = 0; dt < 8; dt++) {
            acc[dt][0] *= al0; acc[dt][1] *= al0;
            acc[dt][2] *= al1; acc[dt][3] *= al1;
        }
        lsum[0] *= al0; lsum[1] *= al0;
        lsum[2] *= al1; lsum[3] *= al1;

        // ---- P: C-frag -> A-frag repack (registers only) ----
        unsigned pa[4][4];
#pragma unroll
        for (int ks = 0; ks < 4; ks++) {
            pa[ks][0] = packh2(sf[2 * ks][0],     sf[2 * ks][1]);
            pa[ks][1] = packh2(sf[2 * ks][2],     sf[2 * ks][3]);
            pa[ks][2] = packh2(sf[2 * ks + 1][0], sf[2 * ks + 1][1]);
            pa[ks][3] = packh2(sf[2 * ks + 1][2], sf[2 * ks + 1][3]);
        }

        // ---- O += P V  (V via ldmatrix.trans); row sums via ones-MMA ----
#pragma unroll
        for (int p = 0; p < 2; p++) {
            const int r = 32 * p + (lane & 7) + (lane >> 3) * 8;
#pragma unroll
            for (int dt = 0; dt < 8; dt++) {
                unsigned vb[4];
                ldm_x4t(vb[0], vb[1], vb[2], vb[3],
                        sptr(vsm + r * 64 + ((dt ^ (r & 7)) << 3)));
                mma16816(acc[dt], pa[2 * p],     vb[0], vb[1]);
                mma16816(acc[dt], pa[2 * p + 1], vb[2], vb[3]);
            }
            mma16816(lsum, pa[2 * p],     ONES_H2, ONES_H2);
            mma16816(lsum, pa[2 * p + 1], ONES_H2, ONES_H2);
        }
    }

    // ---- epilogue ----
    const float il0 = 1.0f / lsum[0];
    const float il1 = 1.0f / lsum[2];
#pragma unroll
    for (int dt = 0; dt < 8; dt++) {
        const int r = q0 + woff + gid;
        const int c = h * HD + dt * 8 + tg * 2;
        *(__half2*)&ctx[(long)r * CTX_N + c] =
            __floats2half2_rn(acc[dt][0] * il0, acc[dt][1] * il0);
        *(__half2*)&ctx[(long)(r + 8) * CTX_N + c] =
            __floats2half2_rn(acc[dt][2] * il1, acc[dt][3] * il1);
    }
}

// ---------------------------------------------------------------------------
extern "C" void kernel_launch(void* const* d_in, const int* in_sizes, int n_in,
                              void* d_out, int out_size) {
    const float* hidden = (const float*)d_in[1];
    const float* w_qkv  = (const float*)d_in[2];
    const float* w_o    = (const float*)d_in[3];
    float* out = (float*)d_out;

    __half *h16, *wq16, *wo16, *qkv, *ctx;
    cudaGetSymbolAddress((void**)&h16,  g_h16);
    cudaGetSymbolAddress((void**)&wq16, g_wq16);
    cudaGetSymbolAddress((void**)&wo16, g_wo16);
    cudaGetSymbolAddress((void**)&qkv,  g_qkv);
    cudaGetSymbolAddress((void**)&ctx,  g_ctx);

    cudaFuncSetAttribute(gemm_tn_h<96, true>,   cudaFuncAttributeMaxDynamicSharedMemorySize, GEMM_SMEM_Q);
    cudaFuncSetAttribute(gemm_tn_h<128, false>, cudaFuncAttributeMaxDynamicSharedMemorySize, GEMM_SMEM_O);
    cudaFuncSetAttribute(flash_attn_h,          cudaFuncAttributeMaxDynamicSharedMemorySize, FA_SMEM);

    // 0) fp32 -> fp16 conversions (single launch, 3 segments)
    f2h3<<<(F2H_TOT + 255) / 256, 256>>>((const float4*)hidden, (__half2*)h16,
                                         (const float4*)w_qkv, (__half2*)wq16,
                                         (const float4*)w_o,   (__half2*)wo16);

    // 1) fused QKV projection -> fp16 (128x96 tiles: 512 CTAs = 2 balanced waves)
    gemm_tn_h<96, true><<<dim3(QKV_N / 96, S_LEN / 128), 256, GEMM_SMEM_Q>>>(h16, wq16, qkv, S_LEN, QKV_N, HID);
    // 2) RoPE (0.125*log2e folded into q)
    rope_h<<<dim3(S_LEN, 5), 256>>>(qkv);
    // 3) causal flash attention (GQA)
    flash_attn_h<<<dim3(S_LEN / 128, NH), 256, FA_SMEM>>>(qkv, ctx);
    // 4) output projection -> fp32 (single wave at 128x128)
    gemm_tn_h<128, false><<<dim3(CTX_N / 128, S_LEN / 128), 256, GEMM_SMEM_O>>>(ctx, wo16, out, S_LEN, CTX_N, CTX_N);
}

// round 12
// speedup vs baseline: 1.2404x; 1.1251x over previous
#include <cuda_runtime.h>
#include <cuda_fp16.h>
#include <math.h>
#include <stdint.h>

#define S_LEN 2048
#define HID   2048
#define NH    32
#define NKV   8
#define HD    64
#define QKV_N 3072
#define CTX_N 2048
#define K_OFF 2048
#define V_OFF 2560

// scratch (no cudaMalloc allowed)
__device__ __half g_h16 [S_LEN * HID];
__device__ __half g_wq16[QKV_N * HID];
__device__ __half g_wo16[HID * CTX_N];
__device__ __half g_qkv [S_LEN * QKV_N];
__device__ __half g_ctx [S_LEN * CTX_N];

// ---------------------------------------------------------------------------
__device__ __forceinline__ unsigned sptr(const void* p) {
    return (unsigned)__cvta_generic_to_shared(p);
}
#define CP_ASYNC16(dst, src) \
    asm volatile("cp.async.cg.shared.global [%0], [%1], 16;\n" :: "r"(dst), "l"(src))
#define CP_COMMIT() asm volatile("cp.async.commit_group;\n")
#define CP_WAIT0()  asm volatile("cp.async.wait_group 0;\n")
#define CP_WAIT1()  asm volatile("cp.async.wait_group 1;\n")
#define CP_WAIT2()  asm volatile("cp.async.wait_group 2;\n")

__device__ __forceinline__ void ldm_x4(unsigned& r0, unsigned& r1, unsigned& r2, unsigned& r3,
                                       unsigned addr) {
    asm volatile("ldmatrix.sync.aligned.m8n8.x4.shared.b16 {%0,%1,%2,%3}, [%4];\n"
                 : "=r"(r0), "=r"(r1), "=r"(r2), "=r"(r3) : "r"(addr));
}
__device__ __forceinline__ void ldm_x4t(unsigned& r0, unsigned& r1, unsigned& r2, unsigned& r3,
                                        unsigned addr) {
    asm volatile("ldmatrix.sync.aligned.m8n8.x4.trans.shared.b16 {%0,%1,%2,%3}, [%4];\n"
                 : "=r"(r0), "=r"(r1), "=r"(r2), "=r"(r3) : "r"(addr));
}
__device__ __forceinline__ void mma16816(float d[4], const unsigned a[4],
                                         unsigned b0, unsigned b1) {
    asm volatile("mma.sync.aligned.m16n8k16.row.col.f32.f16.f16.f32 "
                 "{%0,%1,%2,%3}, {%4,%5,%6,%7}, {%8,%9}, {%0,%1,%2,%3};\n"
                 : "+f"(d[0]), "+f"(d[1]), "+f"(d[2]), "+f"(d[3])
                 : "r"(a[0]), "r"(a[1]), "r"(a[2]), "r"(a[3]), "r"(b0), "r"(b1));
}
__device__ __forceinline__ unsigned packh2(float x, float y) {
    __half2 h = __floats2half2_rn(x, y);
    return *reinterpret_cast<unsigned*>(&h);
}

// ---------------------------------------------------------------------------
// fp32 -> fp16 conversion, 3 segments in one launch
// ---------------------------------------------------------------------------
#define F2H_L0 (S_LEN * HID / 4)
#define F2H_L1 (QKV_N * HID / 4)
#define F2H_L2 (HID * CTX_N / 4)
#define F2H_TOT (F2H_L0 + F2H_L1 + F2H_L2)

__global__ __launch_bounds__(256) void f2h3(const float4* __restrict__ s0, __half2* __restrict__ d0,
                                            const float4* __restrict__ s1, __half2* __restrict__ d1,
                                            const float4* __restrict__ s2, __half2* __restrict__ d2) {
    int i = blockIdx.x * 256 + threadIdx.x;
    const float4* s;
    __half2* d;
    if (i < F2H_L0) { s = s0; d = d0; }
    else if (i < F2H_L0 + F2H_L1) { i -= F2H_L0; s = s1; d = d1; }
    else if (i < F2H_TOT) { i -= F2H_L0 + F2H_L1; s = s2; d = d2; }
    else return;
    const float4 v = s[i];
    d[2 * i]     = __floats2half2_rn(v.x, v.y);
    d[2 * i + 1] = __floats2half2_rn(v.z, v.w);
}

// ---------------------------------------------------------------------------
// C[m][n] = sum_k A[m][k]*B[n][k], fp16 in / fp32 acc.  128 x NT x 32 tiles,
// 256 thr = 8 warps (2m x 4n, warp tile 64 x NT/4), 4-stage cp.async pipeline.
// smem per stage: A[128][32] + B[NT][32], chunk swizzle c^((r>>1)&3).
// ---------------------------------------------------------------------------
#define GNS 4
#define GA_H (128 * 32)

template <int NT, bool HALF_OUT>
__global__ __launch_bounds__(256, 2) void gemm_tn_h(const __half* __restrict__ A,
                                                    const __half* __restrict__ B,
                                                    void* __restrict__ Cv,
                                                    int M, int N, int K) {
    constexpr int GB_H = NT * 32;          // B halves per stage
    constexpr int STG = GA_H + GB_H;       // stage halves
    constexpr int NTL = NT / 32;           // n8-tiles per warp
    constexpr int NBCH = NT * 4;           // B 16B-chunks per stage
    extern __shared__ __half gsm[];
    const int tid  = threadIdx.x;
    const int warp = tid >> 5, lane = tid & 31;
    const int gid  = lane >> 2, tg = lane & 3;
    const int wm   = warp & 1,  wn = warp >> 1;
    const int m0 = blockIdx.y * 128, n0 = blockIdx.x * NT;

    // A loader: 512 chunks (2/thread); B loader: NBCH chunks (guarded)
    int swa[2]; long ga[2];
#pragma unroll
    for (int i = 0; i < 2; i++) {
        const int f = tid + i * 256, r = f >> 2, c = f & 3;
        swa[i] = r * 32 + ((c ^ ((r >> 1) & 3)) << 3);
        ga[i]  = (long)(m0 + r) * K + c * 8;
    }
    int swb[2]; long gb[2];
#pragma unroll
    for (int i = 0; i < 2; i++) {
        const int f = tid + i * 256;
        const int r = (f < NBCH) ? (f >> 2) : 0;
        const int c = f & 3;
        swb[i] = r * 32 + ((c ^ ((r >> 1) & 3)) << 3);
        gb[i]  = (long)(n0 + r) * K + c * 8;
    }

    float acc[4][NTL][4] = {};

#define G_LOAD(IT)                                                      \
    do {                                                                \
        const int kk_ = (IT) << 5;                                      \
        __half* a_ = gsm + ((IT) & (GNS - 1)) * STG;                    \
        __half* b_ = a_ + GA_H;                                         \
        _Pragma("unroll")                                               \
        for (int i_ = 0; i_ < 2; i_++)                                  \
            CP_ASYNC16(sptr(a_ + swa[i_]), A + ga[i_] + kk_);           \
        _Pragma("unroll")                                               \
        for (int i_ = 0; i_ < 2; i_++)                                  \
            if (tid + i_ * 256 < NBCH)                                  \
                CP_ASYNC16(sptr(b_ + swb[i_]), B + gb[i_] + kk_);       \
        CP_COMMIT();                                                    \
    } while (0)

    const int nIter = K >> 5;
    G_LOAD(0); G_LOAD(1); G_LOAD(2);

    for (int it = 0; it < nIter; ++it) {
        if (it + 3 <= nIter)      { CP_WAIT2(); }
        else if (it + 2 == nIter) { CP_WAIT1(); }
        else                      { CP_WAIT0(); }
        __syncthreads();
        if (it + 3 < nIter) G_LOAD(it + 3);

        const __half* a = gsm + (it & (GNS - 1)) * STG;
        const __half* b = a + GA_H;

        unsigned bf[NTL][4];
        {
            const int rb = wn * (NT / 4) + (lane & 7);
            const int cb = lane >> 3;
#pragma unroll
            for (int nt = 0; nt < NTL; nt++) {
                const int r = rb + nt * 8;
                ldm_x4(bf[nt][0], bf[nt][1], bf[nt][2], bf[nt][3],
                       sptr(b + r * 32 + ((cb ^ ((r >> 1) & 3)) << 3)));
            }
        }
#pragma unroll
        for (int p = 0; p < 2; p++) {
            unsigned af[4][4];
            const int ra = wm * 64 + (lane & 7) + ((lane >> 3) & 1) * 8;
            const int ca = p * 2 + ((lane >> 4) & 1);
#pragma unroll
            for (int mt = 0; mt < 4; mt++) {
                const int r = ra + mt * 16;
                ldm_x4(af[mt][0], af[mt][1], af[mt][2], af[mt][3],
                       sptr(a + r * 32 + ((ca ^ ((r >> 1) & 3)) << 3)));
            }
#pragma unroll
            for (int nt = 0; nt < NTL; nt++)
#pragma unroll
                for (int mt = 0; mt < 4; mt++)
                    mma16816(acc[mt][nt], af[mt], bf[nt][2 * p], bf[nt][2 * p + 1]);
        }
    }

#pragma unroll
    for (int mt = 0; mt < 4; mt++)
#pragma unroll
        for (int nt = 0; nt < NTL; nt++) {
            const int r = m0 + wm * 64 + mt * 16 + gid;
            const int c = n0 + wn * (NT / 4) + nt * 8 + tg * 2;
            if (HALF_OUT) {
                __half* C = (__half*)Cv;
                *(__half2*)&C[(long)r * N + c] =
                    __floats2half2_rn(acc[mt][nt][0], acc[mt][nt][1]);
                *(__half2*)&C[(long)(r + 8) * N + c] =
                    __floats2half2_rn(acc[mt][nt][2], acc[mt][nt][3]);
            } else {
                float* C = (float*)Cv;
                *(float2*)&C[(long)r * N + c] = make_float2(acc[mt][nt][0], acc[mt][nt][1]);
                *(float2*)&C[(long)(r + 8) * N + c] = make_float2(acc[mt][nt][2], acc[mt][nt][3]);
            }
        }
}

#define GEMM_SMEM_Q (GNS * (GA_H + 96 * 32) * 2)    // NT=96
#define GEMM_SMEM_O (GNS * (GA_H + 128 * 32) * 2)   // NT=128

// ---------------------------------------------------------------------------
// RoPE (neox) in-place on fp16 q,k.  positions = arange(S).
// Folds 0.125 * log2(e) into q (FA softmax runs in exp2 domain).
// 256 threads = 8 heads per block.
// ---------------------------------------------------------------------------
__global__ __launch_bounds__(256) void rope_h(__half* __restrict__ qkv) {
    const int s  = blockIdx.x;
    const int hh = blockIdx.y * 8 + (threadIdx.x >> 5);
    const int i  = threadIdx.x & 31;
    const int base = (hh < NH) ? hh * HD : (K_OFF + (hh - NH) * HD);
    const float qs = (hh < NH) ? 0.125f * 1.44269504f : 1.0f;
    const float inv = powf(10000.0f, -(2.0f * (float)i) / 64.0f);
    const float ang = (float)s * inv;
    const float c = cosf(ang), sn = sinf(ang);
    __half* row = qkv + (long)s * QKV_N + base;
    const float x1 = __half2float(row[i]);
    const float x2 = __half2float(row[i + 32]);
    row[i]      = __float2half_rn((x1 * c - x2 * sn) * qs);
    row[i + 32] = __float2half_rn((x2 * c + x1 * sn) * qs);
}

// ---------------------------------------------------------------------------
// Causal flash attention, fp16 mma.  128 q-rows/block, 8 warps (16 rows each),
// 3-stage K/V cp.async pipeline, V via ldmatrix.x4.trans, P stays in regs.
// Stale-max online softmax: iter j exponentiates with the true max through
// tile j-1; the shuffle max-reduce runs in the shadow of the PV MMAs and
// yields the rescale factor consumed next iteration.  Basis cancels in O/l.
// Row sums via MMA against all-ones B fragment.
// ---------------------------------------------------------------------------
#define FQ_H (128 * 64)
#define FKV_H (64 * 64)
#define FA_SMEM ((FQ_H + 3 * 2 * FKV_H) * 2)
#define ONES_H2 0x3C003C00u

__global__ __launch_bounds__(256, 2) void flash_attn_h(const __half* __restrict__ qkv,
                                                       __half* __restrict__ ctx) {
    extern __shared__ __half fsm[];
    __half* Qs = fsm;   // [128][64]

    const int qt  = (S_LEN / 128 - 1) - blockIdx.y;   // longest tiles first, heads fastest
    const int h   = blockIdx.x;
    const int kvh = h >> 2;
    const int tid = threadIdx.x, warp = tid >> 5, lane = tid & 31;
    const int gid = lane >> 2, tg = lane & 3;
    const int q0 = qt * 128, woff = warp * 16;
    const int jmax = (q0 + 127) >> 6;

    int rr[2], cc8[2], sw[2];
#pragma unroll
    for (int i = 0; i < 2; i++) {
        const int f = tid + i * 256;
        const int r = f >> 3, c = f & 7;
        rr[i] = r; cc8[i] = c * 8;
        sw[i] = r * 64 + ((c ^ (r & 7)) << 3);
    }

#define FA_LOADKV(J)                                                                     \
    do {                                                                                 \
        const int kb_ = (J) * 64;                                                        \
        __half* kd_ = fsm + FQ_H + ((J) % 3) * 2 * FKV_H;                                \
        __half* vd_ = kd_ + FKV_H;                                                       \
        _Pragma("unroll")                                                                \
        for (int i_ = 0; i_ < 2; i_++) {                                                 \
            CP_ASYNC16(sptr(kd_ + sw[i_]),                                               \
                       qkv + (long)(kb_ + rr[i_]) * QKV_N + K_OFF + kvh * HD + cc8[i_]); \
            CP_ASYNC16(sptr(vd_ + sw[i_]),                                               \
                       qkv + (long)(kb_ + rr[i_]) * QKV_N + V_OFF + kvh * HD + cc8[i_]); \
        }                                                                                \
        CP_COMMIT();                                                                     \
    } while (0)

    // prologue: Q (1024 chunks, 4/thread) then KV0, KV1
#pragma unroll
    for (int i = 0; i < 4; i++) {
        const int f = tid + i * 256;
        const int r = f >> 3, c = f & 7;
        CP_ASYNC16(sptr(Qs + r * 64 + ((c ^ (r & 7)) << 3)),
                   qkv + (long)(q0 + r) * QKV_N + h * HD + c * 8);
    }
    CP_COMMIT();
    FA_LOADKV(0);
    FA_LOADKV(1);

    CP_WAIT2();          // Q done (KV0, KV1 may be in flight)
    __syncthreads();

    unsigned qa[4][4];
    {
        const int r = woff + (lane & 7) + ((lane >> 3) & 1) * 8;
        const int cb = (lane >> 4) & 1;
#pragma unroll
        for (int ks = 0; ks < 4; ks++) {
            const int c = 2 * ks + cb;
            ldm_x4(qa[ks][0], qa[ks][1], qa[ks][2], qa[ks][3],
                   sptr(Qs + r * 64 + ((c ^ (r & 7)) << 3)));
        }
    }

    float acc[8][4] = {};
    float lsum[4] = {};
    float b0 = 0.0f, b1 = 0.0f;     // current exp basis
    float al0 = 1.0f, al1 = 1.0f;   // rescale factor pending for next iter
    bool first = true;

    for (int j = 0; j <= jmax; ++j) {
        if (j < jmax) { CP_WAIT1(); } else { CP_WAIT0(); }
        __syncthreads();
        if (j + 2 <= jmax) FA_LOADKV(j + 2);

        // skip fully-masked iterations for this warp (still did sync+prefetch)
        if ((j << 6) > q0 + woff + 15) continue;

        const __half* ksm = fsm + FQ_H + (j % 3) * 2 * FKV_H;
        const __half* vsm = ksm + FKV_H;

        // ---- S = Q K^T ----
        float sf[8][4] = {};
#pragma unroll
        for (int p = 0; p < 2; p++) {
            const int rb = lane & 7;
            const int cb = 4 * p + (lane >> 3);
#pragma unroll
            for (int nt = 0; nt < 8; nt++) {
                unsigned kb[4];
                const int r = nt * 8 + rb;
                ldm_x4(kb[0], kb[1], kb[2], kb[3],
                       sptr(ksm + r * 64 + ((cb ^ (r & 7)) << 3)));
                mma16816(sf[nt], qa[2 * p],     kb[0], kb[1]);
                mma16816(sf[nt], qa[2 * p + 1], kb[2], kb[3]);
            }
        }

        // ---- causal mask (absolute coords; only near diagonal) ----
        if ((j << 6) + 63 > q0 + woff) {
            const int r0m = q0 + woff + gid;
            const int r1m = r0m + 8;
#pragma unroll
            for (int nt = 0; nt < 8; nt++) {
                const int c0 = (j << 6) + nt * 8 + tg * 2;
                if (c0 > r0m)     sf[nt][0] = -INFINITY;
                if (c0 + 1 > r0m) sf[nt][1] = -INFINITY;
                if (c0 > r1m)     sf[nt][2] = -INFINITY;
                if (c0 + 1 > r1m) sf[nt][3] = -INFINITY;
            }
        }

        // ---- local (per-thread) row max of raw scores ----
        float mx0 = sf[0][0], mx1 = sf[0][2];
#pragma unroll
        for (int nt = 0; nt < 8; nt++) {
            mx0 = fmaxf(mx0, fmaxf(sf[nt][0], sf[nt][1]));
            mx1 = fmaxf(mx1, fmaxf(sf[nt][2], sf[nt][3]));
        }

        if (first) {
            // exact path once per warp: reduce max across quad before exp
            mx0 = fmaxf(mx0, __shfl_xor_sync(0xffffffffu, mx0, 1));
            mx0 = fmaxf(mx0, __shfl_xor_sync(0xffffffffu, mx0, 2));
            mx1 = fmaxf(mx1, __shfl_xor_sync(0xffffffffu, mx1, 1));
            mx1 = fmaxf(mx1, __shfl_xor_sync(0xffffffffu, mx1, 2));
            b0 = mx0; b1 = mx1;
            first = false;
        } else {
            // apply rescale factor produced by previous iteration's reduce
#pragma unroll
            for (int dt = 0; dt < 8; dt++) {
                acc[dt][0] *= al0; acc[dt][1] *= al0;
                acc[dt][2] *= al1; acc[dt][3] *= al1;
            }
            lsum[0] *= al0; lsum[1] *= al0;
            lsum[2] *= al1; lsum[3] *= al1;
        }

        // ---- exp with (possibly stale) basis b ----
#pragma unroll
        for (int nt = 0; nt < 8; nt++) {
            sf[nt][0] = exp2f(sf[nt][0] - b0);
            sf[nt][1] = exp2f(sf[nt][1] - b0);
            sf[nt][2] = exp2f(sf[nt][2] - b1);
            sf[nt][3] = exp2f(sf[nt][3] - b1);
        }

        // ---- P: C-frag -> A-frag repack (registers only) ----
        unsigned pa[4][4];
#pragma unroll
        for (int ks = 0; ks < 4; ks++) {
            pa[ks][0] = packh2(sf[2 * ks][0],     sf[2 * ks][1]);
            pa[ks][1] = packh2(sf[2 * ks][2],     sf[2 * ks][3]);
            pa[ks][2] = packh2(sf[2 * ks + 1][0], sf[2 * ks + 1][1]);
            pa[ks][3] = packh2(sf[2 * ks + 1][2], sf[2 * ks + 1][3]);
        }

        // ---- O += P V  (V via ldmatrix.trans); row sums via ones-MMA ----
#pragma unroll
        for (int p = 0; p < 2; p++) {
            const int r = 32 * p + (lane & 7) + (lane >> 3) * 8;
#pragma unroll
            for (int dt = 0; dt < 8; dt++) {
                unsigned vb[4];
                ldm_x4t(vb[0], vb[1], vb[2], vb[3],
                        sptr(vsm + r * 64 + ((dt ^ (r & 7)) << 3)));
                mma16816(acc[dt], pa[2 * p],     vb[0], vb[1]);
                mma16816(acc[dt], pa[2 * p + 1], vb[2], vb[3]);
            }
            mma16816(lsum, pa[2 * p],     ONES_H2, ONES_H2);
            mma16816(lsum, pa[2 * p + 1], ONES_H2, ONES_H2);
        }

        // ---- deferred max update (runs in the MMA shadow) ----
        mx0 = fmaxf(mx0, __shfl_xor_sync(0xffffffffu, mx0, 1));
        mx0 = fmaxf(mx0, __shfl_xor_sync(0xffffffffu, mx0, 2));
        mx1 = fmaxf(mx1, __shfl_xor_sync(0xffffffffu, mx1, 1));
        mx1 = fmaxf(mx1, __shfl_xor_sync(0xffffffffu, mx1, 2));
        const float bn0 = fmaxf(b0, mx0);
        const float bn1 = fmaxf(b1, mx1);
        al0 = exp2f(b0 - bn0);
        al1 = exp2f(b1 - bn1);
        b0 = bn0; b1 = bn1;
    }

    // ---- epilogue (basis cancels in O/l) ----
    const float il0 = 1.0f / lsum[0];
    const float il1 = 1.0f / lsum[2];
#pragma unroll
    for (int dt = 0; dt < 8; dt++) {
        const int r = q0 + woff + gid;
        const int c = h * HD + dt * 8 + tg * 2;
        *(__half2*)&ctx[(long)r * CTX_N + c] =
            __floats2half2_rn(acc[dt][0] * il0, acc[dt][1] * il0);
        *(__half2*)&ctx[(long)(r + 8) * CTX_N + c] =
            __floats2half2_rn(acc[dt][2] * il1, acc[dt][3] * il1);
    }
}

// ---------------------------------------------------------------------------
extern "C" void kernel_launch(void* const* d_in, const int* in_sizes, int n_in,
                              void* d_out, int out_size) {
    const float* hidden = (const float*)d_in[1];
    const float* w_qkv  = (const float*)d_in[2];
    const float* w_o    = (const float*)d_in[3];
    float* out = (float*)d_out;

    __half *h16, *wq16, *wo16, *qkv, *ctx;
    cudaGetSymbolAddress((void**)&h16,  g_h16);
    cudaGetSymbolAddress((void**)&wq16, g_wq16);
    cudaGetSymbolAddress((void**)&wo16, g_wo16);
    cudaGetSymbolAddress((void**)&qkv,  g_qkv);
    cudaGetSymbolAddress((void**)&ctx,  g_ctx);

    cudaFuncSetAttribute(gemm_tn_h<96, true>,   cudaFuncAttributeMaxDynamicSharedMemorySize, GEMM_SMEM_Q);
    cudaFuncSetAttribute(gemm_tn_h<128, false>, cudaFuncAttributeMaxDynamicSharedMemorySize, GEMM_SMEM_O);
    cudaFuncSetAttribute(flash_attn_h,          cudaFuncAttributeMaxDynamicSharedMemorySize, FA_SMEM);

    // 0) fp32 -> fp16 conversions (single launch, 3 segments)
    f2h3<<<(F2H_TOT + 255) / 256, 256>>>((const float4*)hidden, (__half2*)h16,
                                         (const float4*)w_qkv, (__half2*)wq16,
                                         (const float4*)w_o,   (__half2*)wo16);

    // 1) fused QKV projection -> fp16 (128x96 tiles)
    gemm_tn_h<96, true><<<dim3(QKV_N / 96, S_LEN / 128), 256, GEMM_SMEM_Q>>>(h16, wq16, qkv, S_LEN, QKV_N, HID);
    // 2) RoPE (0.125*log2e folded into q)
    rope_h<<<dim3(S_LEN, 5), 256>>>(qkv);
    // 3) causal flash attention (GQA; heads fastest, longest q-tiles first)
    flash_attn_h<<<dim3(NH, S_LEN / 128), 256, FA_SMEM>>>(qkv, ctx);
    // 4) output projection -> fp32 (single wave at 128x128)
    gemm_tn_h<128, false><<<dim3(CTX_N / 128, S_LEN / 128), 256, GEMM_SMEM_O>>>(ctx, wo16, out, S_LEN, CTX_N, CTX_N);
}

// round 13
// speedup vs baseline: 1.2634x; 1.0186x over previous
#include <cuda_runtime.h>
#include <cuda_fp16.h>
#include <math.h>
#include <stdint.h>

#define S_LEN 2048
#define HID   2048
#define NH    32
#define NKV   8
#define HD    64
#define QKV_N 3072
#define CTX_N 2048
#define K_OFF 2048
#define V_OFF 2560

// scratch (no cudaMalloc allowed)
__device__ __half g_h16 [S_LEN * HID];
__device__ __half g_wq16[QKV_N * HID];
__device__ __half g_wo16[HID * CTX_N];
__device__ __half g_qkv [S_LEN * QKV_N];
__device__ __half g_ctx [S_LEN * CTX_N];

// ---------------------------------------------------------------------------
__device__ __forceinline__ unsigned sptr(const void* p) {
    return (unsigned)__cvta_generic_to_shared(p);
}
#define CP_ASYNC16(dst, src) \
    asm volatile("cp.async.cg.shared.global [%0], [%1], 16;\n" :: "r"(dst), "l"(src))
#define CP_COMMIT() asm volatile("cp.async.commit_group;\n")
#define CP_WAIT0()  asm volatile("cp.async.wait_group 0;\n")
#define CP_WAIT1()  asm volatile("cp.async.wait_group 1;\n")
#define CP_WAIT2()  asm volatile("cp.async.wait_group 2;\n")

__device__ __forceinline__ void ldm_x4(unsigned& r0, unsigned& r1, unsigned& r2, unsigned& r3,
                                       unsigned addr) {
    asm volatile("ldmatrix.sync.aligned.m8n8.x4.shared.b16 {%0,%1,%2,%3}, [%4];\n"
                 : "=r"(r0), "=r"(r1), "=r"(r2), "=r"(r3) : "r"(addr));
}
__device__ __forceinline__ void ldm_x4t(unsigned& r0, unsigned& r1, unsigned& r2, unsigned& r3,
                                        unsigned addr) {
    asm volatile("ldmatrix.sync.aligned.m8n8.x4.trans.shared.b16 {%0,%1,%2,%3}, [%4];\n"
                 : "=r"(r0), "=r"(r1), "=r"(r2), "=r"(r3) : "r"(addr));
}
__device__ __forceinline__ void mma16816(float d[4], const unsigned a[4],
                                         unsigned b0, unsigned b1) {
    asm volatile("mma.sync.aligned.m16n8k16.row.col.f32.f16.f16.f32 "
                 "{%0,%1,%2,%3}, {%4,%5,%6,%7}, {%8,%9}, {%0,%1,%2,%3};\n"
                 : "+f"(d[0]), "+f"(d[1]), "+f"(d[2]), "+f"(d[3])
                 : "r"(a[0]), "r"(a[1]), "r"(a[2]), "r"(a[3]), "r"(b0), "r"(b1));
}
__device__ __forceinline__ unsigned packh2(float x, float y) {
    __half2 h = __floats2half2_rn(x, y);
    return *reinterpret_cast<unsigned*>(&h);
}
// fast exp2: single MUFU, guaranteed approx lowering regardless of compile flags
__device__ __forceinline__ float ex2(float x) {
    float r;
    asm("ex2.approx.ftz.f32 %0, %1;" : "=f"(r) : "f"(x));
    return r;
}

// ---------------------------------------------------------------------------
// fp32 -> fp16 conversion, 3 segments in one launch
// ---------------------------------------------------------------------------
#define F2H_L0 (S_LEN * HID / 4)
#define F2H_L1 (QKV_N * HID / 4)
#define F2H_L2 (HID * CTX_N / 4)
#define F2H_TOT (F2H_L0 + F2H_L1 + F2H_L2)

__global__ __launch_bounds__(256) void f2h3(const float4* __restrict__ s0, __half2* __restrict__ d0,
                                            const float4* __restrict__ s1, __half2* __restrict__ d1,
                                            const float4* __restrict__ s2, __half2* __restrict__ d2) {
    int i = blockIdx.x * 256 + threadIdx.x;
    const float4* s;
    __half2* d;
    if (i < F2H_L0) { s = s0; d = d0; }
    else if (i < F2H_L0 + F2H_L1) { i -= F2H_L0; s = s1; d = d1; }
    else if (i < F2H_TOT) { i -= F2H_L0 + F2H_L1; s = s2; d = d2; }
    else return;
    const float4 v = s[i];
    d[2 * i]     = __floats2half2_rn(v.x, v.y);
    d[2 * i + 1] = __floats2half2_rn(v.z, v.w);
}

// ---------------------------------------------------------------------------
// C[m][n] = sum_k A[m][k]*B[n][k], fp16 in / fp32 acc.  128 x NT x 32 tiles,
// 256 thr = 8 warps (2m x 4n, warp tile 64 x NT/4), 4-stage cp.async pipeline.
// smem per stage: A[128][32] + B[NT][32], chunk swizzle c^((r>>1)&3).
// ---------------------------------------------------------------------------
#define GNS 4
#define GA_H (128 * 32)

template <int NT, bool HALF_OUT>
__global__ __launch_bounds__(256, 2) void gemm_tn_h(const __half* __restrict__ A,
                                                    const __half* __restrict__ B,
                                                    void* __restrict__ Cv,
                                                    int M, int N, int K) {
    constexpr int GB_H = NT * 32;          // B halves per stage
    constexpr int STG = GA_H + GB_H;       // stage halves
    constexpr int NTL = NT / 32;           // n8-tiles per warp
    constexpr int NBCH = NT * 4;           // B 16B-chunks per stage
    extern __shared__ __half gsm[];
    const int tid  = threadIdx.x;
    const int warp = tid >> 5, lane = tid & 31;
    const int gid  = lane >> 2, tg = lane & 3;
    const int wm   = warp & 1,  wn = warp >> 1;
    const int m0 = blockIdx.y * 128, n0 = blockIdx.x * NT;

    // A loader: 512 chunks (2/thread); B loader: NBCH chunks (guarded)
    int swa[2]; long ga[2];
#pragma unroll
    for (int i = 0; i < 2; i++) {
        const int f = tid + i * 256, r = f >> 2, c = f & 3;
        swa[i] = r * 32 + ((c ^ ((r >> 1) & 3)) << 3);
        ga[i]  = (long)(m0 + r) * K + c * 8;
    }
    int swb[2]; long gb[2];
#pragma unroll
    for (int i = 0; i < 2; i++) {
        const int f = tid + i * 256;
        const int r = (f < NBCH) ? (f >> 2) : 0;
        const int c = f & 3;
        swb[i] = r * 32 + ((c ^ ((r >> 1) & 3)) << 3);
        gb[i]  = (long)(n0 + r) * K + c * 8;
    }

    float acc[4][NTL][4] = {};

#define G_LOAD(IT)                                                      \
    do {                                                                \
        const int kk_ = (IT) << 5;                                      \
        __half* a_ = gsm + ((IT) & (GNS - 1)) * STG;                    \
        __half* b_ = a_ + GA_H;                                         \
        _Pragma("unroll")                                               \
        for (int i_ = 0; i_ < 2; i_++)                                  \
            CP_ASYNC16(sptr(a_ + swa[i_]), A + ga[i_] + kk_);           \
        _Pragma("unroll")                                               \
        for (int i_ = 0; i_ < 2; i_++)                                  \
            if (tid + i_ * 256 < NBCH)                                  \
                CP_ASYNC16(sptr(b_ + swb[i_]), B + gb[i_] + kk_);       \
        CP_COMMIT();                                                    \
    } while (0)

    const int nIter = K >> 5;
    G_LOAD(0); G_LOAD(1); G_LOAD(2);

    for (int it = 0; it < nIter; ++it) {
        if (it + 3 <= nIter)      { CP_WAIT2(); }
        else if (it + 2 == nIter) { CP_WAIT1(); }
        else                      { CP_WAIT0(); }
        __syncthreads();
        if (it + 3 < nIter) G_LOAD(it + 3);

        const __half* a = gsm + (it & (GNS - 1)) * STG;
        const __half* b = a + GA_H;

        unsigned bf[NTL][4];
        {
            const int rb = wn * (NT / 4) + (lane & 7);
            const int cb = lane >> 3;
#pragma unroll
            for (int nt = 0; nt < NTL; nt++) {
                const int r = rb + nt * 8;
                ldm_x4(bf[nt][0], bf[nt][1], bf[nt][2], bf[nt][3],
                       sptr(b + r * 32 + ((cb ^ ((r >> 1) & 3)) << 3)));
            }
        }
#pragma unroll
        for (int p = 0; p < 2; p++) {
            unsigned af[4][4];
            const int ra = wm * 64 + (lane & 7) + ((lane >> 3) & 1) * 8;
            const int ca = p * 2 + ((lane >> 4) & 1);
#pragma unroll
            for (int mt = 0; mt < 4; mt++) {
                const int r = ra + mt * 16;
                ldm_x4(af[mt][0], af[mt][1], af[mt][2], af[mt][3],
                       sptr(a + r * 32 + ((ca ^ ((r >> 1) & 3)) << 3)));
            }
#pragma unroll
            for (int nt = 0; nt < NTL; nt++)
#pragma unroll
                for (int mt = 0; mt < 4; mt++)
                    mma16816(acc[mt][nt], af[mt], bf[nt][2 * p], bf[nt][2 * p + 1]);
        }
    }

#pragma unroll
    for (int mt = 0; mt < 4; mt++)
#pragma unroll
        for (int nt = 0; nt < NTL; nt++) {
            const int r = m0 + wm * 64 + mt * 16 + gid;
            const int c = n0 + wn * (NT / 4) + nt * 8 + tg * 2;
            if (HALF_OUT) {
                __half* C = (__half*)Cv;
                *(__half2*)&C[(long)r * N + c] =
                    __floats2half2_rn(acc[mt][nt][0], acc[mt][nt][1]);
                *(__half2*)&C[(long)(r + 8) * N + c] =
                    __floats2half2_rn(acc[mt][nt][2], acc[mt][nt][3]);
            } else {
                float* C = (float*)Cv;
                *(float2*)&C[(long)r * N + c] = make_float2(acc[mt][nt][0], acc[mt][nt][1]);
                *(float2*)&C[(long)(r + 8) * N + c] = make_float2(acc[mt][nt][2], acc[mt][nt][3]);
            }
        }
}

#define GEMM_SMEM_Q (GNS * (GA_H + 96 * 32) * 2)    // NT=96
#define GEMM_SMEM_O (GNS * (GA_H + 128 * 32) * 2)   // NT=128

// ---------------------------------------------------------------------------
// RoPE (neox) in-place on fp16 q,k.  positions = arange(S).
// Folds 0.125 * log2(e) into q (FA softmax runs in exp2 domain).
// 256 threads = 8 heads per block.
// ---------------------------------------------------------------------------
__global__ __launch_bounds__(256) void rope_h(__half* __restrict__ qkv) {
    const int s  = blockIdx.x;
    const int hh = blockIdx.y * 8 + (threadIdx.x >> 5);
    const int i  = threadIdx.x & 31;
    const int base = (hh < NH) ? hh * HD : (K_OFF + (hh - NH) * HD);
    const float qs = (hh < NH) ? 0.125f * 1.44269504f : 1.0f;
    const float inv = powf(10000.0f, -(2.0f * (float)i) / 64.0f);
    const float ang = (float)s * inv;
    const float c = cosf(ang), sn = sinf(ang);
    __half* row = qkv + (long)s * QKV_N + base;
    const float x1 = __half2float(row[i]);
    const float x2 = __half2float(row[i + 32]);
    row[i]      = __float2half_rn((x1 * c - x2 * sn) * qs);
    row[i + 32] = __float2half_rn((x2 * c + x1 * sn) * qs);
}

// ---------------------------------------------------------------------------
// Causal flash attention, fp16 mma.  128 q-rows/block, 8 warps (16 rows each),
// 3-stage K/V cp.async pipeline, V via ldmatrix.x4.trans, P stays in regs.
// Stale-max online softmax; exp via explicit ex2.approx (single MUFU).
// Row sums via MMA against all-ones B fragment.
// ---------------------------------------------------------------------------
#define FQ_H (128 * 64)
#define FKV_H (64 * 64)
#define FA_SMEM ((FQ_H + 3 * 2 * FKV_H) * 2)
#define ONES_H2 0x3C003C00u

__global__ __launch_bounds__(256, 2) void flash_attn_h(const __half* __restrict__ qkv,
                                                       __half* __restrict__ ctx) {
    extern __shared__ __half fsm[];
    __half* Qs = fsm;   // [128][64]

    const int qt  = (S_LEN / 128 - 1) - blockIdx.y;   // longest tiles first, heads fastest
    const int h   = blockIdx.x;
    const int kvh = h >> 2;
    const int tid = threadIdx.x, warp = tid >> 5, lane = tid & 31;
    const int gid = lane >> 2, tg = lane & 3;
    const int q0 = qt * 128, woff = warp * 16;
    const int jmax = (q0 + 127) >> 6;

    int rr[2], cc8[2], sw[2];
#pragma unroll
    for (int i = 0; i < 2; i++) {
        const int f = tid + i * 256;
        const int r = f >> 3, c = f & 7;
        rr[i] = r; cc8[i] = c * 8;
        sw[i] = r * 64 + ((c ^ (r & 7)) << 3);
    }

#define FA_LOADKV(J)                                                                     \
    do {                                                                                 \
        const int kb_ = (J) * 64;                                                        \
        __half* kd_ = fsm + FQ_H + ((J) % 3) * 2 * FKV_H;                                \
        __half* vd_ = kd_ + FKV_H;                                                       \
        _Pragma("unroll")                                                                \
        for (int i_ = 0; i_ < 2; i_++) {                                                 \
            CP_ASYNC16(sptr(kd_ + sw[i_]),                                               \
                       qkv + (long)(kb_ + rr[i_]) * QKV_N + K_OFF + kvh * HD + cc8[i_]); \
            CP_ASYNC16(sptr(vd_ + sw[i_]),                                               \
                       qkv + (long)(kb_ + rr[i_]) * QKV_N + V_OFF + kvh * HD + cc8[i_]); \
        }                                                                                \
        CP_COMMIT();                                                                     \
    } while (0)

    // prologue: Q (1024 chunks, 4/thread) then KV0, KV1
#pragma unroll
    for (int i = 0; i < 4; i++) {
        const int f = tid + i * 256;
        const int r = f >> 3, c = f & 7;
        CP_ASYNC16(sptr(Qs + r * 64 + ((c ^ (r & 7)) << 3)),
                   qkv + (long)(q0 + r) * QKV_N + h * HD + c * 8);
    }
    CP_COMMIT();
    FA_LOADKV(0);
    FA_LOADKV(1);

    CP_WAIT2();          // Q done (KV0, KV1 may be in flight)
    __syncthreads();

    unsigned qa[4][4];
    {
        const int r = woff + (lane & 7) + ((lane >> 3) & 1) * 8;
        const int cb = (lane >> 4) & 1;
#pragma unroll
        for (int ks = 0; ks < 4; ks++) {
            const int c = 2 * ks + cb;
            ldm_x4(qa[ks][0], qa[ks][1], qa[ks][2], qa[ks][3],
                   sptr(Qs + r * 64 + ((c ^ (r & 7)) << 3)));
        }
    }

    float acc[8][4] = {};
    float lsum[4] = {};
    float b0 = 0.0f, b1 = 0.0f;     // current exp basis
    float al0 = 1.0f, al1 = 1.0f;   // rescale factor pending for next iter
    bool first = true;

    for (int j = 0; j <= jmax; ++j) {
        if (j < jmax) { CP_WAIT1(); } else { CP_WAIT0(); }
        __syncthreads();
        if (j + 2 <= jmax) FA_LOADKV(j + 2);

        // skip fully-masked iterations for this warp (still did sync+prefetch)
        if ((j << 6) > q0 + woff + 15) continue;

        const __half* ksm = fsm + FQ_H + (j % 3) * 2 * FKV_H;
        const __half* vsm = ksm + FKV_H;

        // ---- S = Q K^T ----
        float sf[8][4] = {};
#pragma unroll
        for (int p = 0; p < 2; p++) {
            const int rb = lane & 7;
            const int cb = 4 * p + (lane >> 3);
#pragma unroll
            for (int nt = 0; nt < 8; nt++) {
                unsigned kb[4];
                const int r = nt * 8 + rb;
                ldm_x4(kb[0], kb[1], kb[2], kb[3],
                       sptr(ksm + r * 64 + ((cb ^ (r & 7)) << 3)));
                mma16816(sf[nt], qa[2 * p],     kb[0], kb[1]);
                mma16816(sf[nt], qa[2 * p + 1], kb[2], kb[3]);
            }
        }

        // ---- causal mask (absolute coords; only near diagonal) ----
        if ((j << 6) + 63 > q0 + woff) {
            const int r0m = q0 + woff + gid;
            const int r1m = r0m + 8;
#pragma unroll
            for (int nt = 0; nt < 8; nt++) {
                const int c0 = (j << 6) + nt * 8 + tg * 2;
                if (c0 > r0m)     sf[nt][0] = -INFINITY;
                if (c0 + 1 > r0m) sf[nt][1] = -INFINITY;
                if (c0 > r1m)     sf[nt][2] = -INFINITY;
                if (c0 + 1 > r1m) sf[nt][3] = -INFINITY;
            }
        }

        // ---- local (per-thread) row max of raw scores ----
        float mx0 = sf[0][0], mx1 = sf[0][2];
#pragma unroll
        for (int nt = 0; nt < 8; nt++) {
            mx0 = fmaxf(mx0, fmaxf(sf[nt][0], sf[nt][1]));
            mx1 = fmaxf(mx1, fmaxf(sf[nt][2], sf[nt][3]));
        }

        if (first) {
            // exact path once per warp: reduce max across quad before exp
            mx0 = fmaxf(mx0, __shfl_xor_sync(0xffffffffu, mx0, 1));
            mx0 = fmaxf(mx0, __shfl_xor_sync(0xffffffffu, mx0, 2));
            mx1 = fmaxf(mx1, __shfl_xor_sync(0xffffffffu, mx1, 1));
            mx1 = fmaxf(mx1, __shfl_xor_sync(0xffffffffu, mx1, 2));
            b0 = mx0; b1 = mx1;
            first = false;
        } else {
            // apply rescale factor produced by previous iteration's reduce
#pragma unroll
            for (int dt = 0; dt < 8; dt++) {
                acc[dt][0] *= al0; acc[dt][1] *= al0;
                acc[dt][2] *= al1; acc[dt][3] *= al1;
            }
            lsum[0] *= al0; lsum[1] *= al0;
            lsum[2] *= al1; lsum[3] *= al1;
        }

        // ---- exp with (possibly stale) basis b (ex2.approx) ----
#pragma unroll
        for (int nt = 0; nt < 8; nt++) {
            sf[nt][0] = ex2(sf[nt][0] - b0);
            sf[nt][1] = ex2(sf[nt][1] - b0);
            sf[nt][2] = ex2(sf[nt][2] - b1);
            sf[nt][3] = ex2(sf[nt][3] - b1);
        }

        // ---- P: C-frag -> A-frag repack (registers only) ----
        unsigned pa[4][4];
#pragma unroll
        for (int ks = 0; ks < 4; ks++) {
            pa[ks][0] = packh2(sf[2 * ks][0],     sf[2 * ks][1]);
            pa[ks][1] = packh2(sf[2 * ks][2],     sf[2 * ks][3]);
            pa[ks][2] = packh2(sf[2 * ks + 1][0], sf[2 * ks + 1][1]);
            pa[ks][3] = packh2(sf[2 * ks + 1][2], sf[2 * ks + 1][3]);
        }

        // ---- O += P V  (V via ldmatrix.trans); row sums via ones-MMA ----
#pragma unroll
        for (int p = 0; p < 2; p++) {
            const int r = 32 * p + (lane & 7) + (lane >> 3) * 8;
#pragma unroll
            for (int dt = 0; dt < 8; dt++) {
                unsigned vb[4];
                ldm_x4t(vb[0], vb[1], vb[2], vb[3],
                        sptr(vsm + r * 64 + ((dt ^ (r & 7)) << 3)));
                mma16816(acc[dt], pa[2 * p],     vb[0], vb[1]);
                mma16816(acc[dt], pa[2 * p + 1], vb[2], vb[3]);
            }
            mma16816(lsum, pa[2 * p],     ONES_H2, ONES_H2);
            mma16816(lsum, pa[2 * p + 1], ONES_H2, ONES_H2);
        }

        // ---- deferred max update (runs in the MMA shadow) ----
        mx0 = fmaxf(mx0, __shfl_xor_sync(0xffffffffu, mx0, 1));
        mx0 = fmaxf(mx0, __shfl_xor_sync(0xffffffffu, mx0, 2));
        mx1 = fmaxf(mx1, __shfl_xor_sync(0xffffffffu, mx1, 1));
        mx1 = fmaxf(mx1, __shfl_xor_sync(0xffffffffu, mx1, 2));
        const float bn0 = fmaxf(b0, mx0);
        const float bn1 = fmaxf(b1, mx1);
        al0 = ex2(b0 - bn0);
        al1 = ex2(b1 - bn1);
        b0 = bn0; b1 = bn1;
    }

    // ---- epilogue (basis cancels in O/l) ----
    const float il0 = 1.0f / lsum[0];
    const float il1 = 1.0f / lsum[2];
#pragma unroll
    for (int dt = 0; dt < 8; dt++) {
        const int r = q0 + woff + gid;
        const int c = h * HD + dt * 8 + tg * 2;
        *(__half2*)&ctx[(long)r * CTX_N + c] =
            __floats2half2_rn(acc[dt][0] * il0, acc[dt][1] * il0);
        *(__half2*)&ctx[(long)(r + 8) * CTX_N + c] =
            __floats2half2_rn(acc[dt][2] * il1, acc[dt][3] * il1);
    }
}

// ---------------------------------------------------------------------------
extern "C" void kernel_launch(void* const* d_in, const int* in_sizes, int n_in,
                              void* d_out, int out_size) {
    const float* hidden = (const float*)d_in[1];
    const float* w_qkv  = (const float*)d_in[2];
    const float* w_o    = (const float*)d_in[3];
    float* out = (float*)d_out;

    __half *h16, *wq16, *wo16, *qkv, *ctx;
    cudaGetSymbolAddress((void**)&h16,  g_h16);
    cudaGetSymbolAddress((void**)&wq16, g_wq16);
    cudaGetSymbolAddress((void**)&wo16, g_wo16);
    cudaGetSymbolAddress((void**)&qkv,  g_qkv);
    cudaGetSymbolAddress((void**)&ctx,  g_ctx);

    cudaFuncSetAttribute(gemm_tn_h<96, true>,   cudaFuncAttributeMaxDynamicSharedMemorySize, GEMM_SMEM_Q);
    cudaFuncSetAttribute(gemm_tn_h<128, false>, cudaFuncAttributeMaxDynamicSharedMemorySize, GEMM_SMEM_O);
    cudaFuncSetAttribute(flash_attn_h,          cudaFuncAttributeMaxDynamicSharedMemorySize, FA_SMEM);

    // 0) fp32 -> fp16 conversions (single launch, 3 segments)
    f2h3<<<(F2H_TOT + 255) / 256, 256>>>((const float4*)hidden, (__half2*)h16,
                                         (const float4*)w_qkv, (__half2*)wq16,
                                         (const float4*)w_o,   (__half2*)wo16);

    // 1) fused QKV projection -> fp16 (128x96 tiles)
    gemm_tn_h<96, true><<<dim3(QKV_N / 96, S_LEN / 128), 256, GEMM_SMEM_Q>>>(h16, wq16, qkv, S_LEN, QKV_N, HID);
    // 2) RoPE (0.125*log2e folded into q)
    rope_h<<<dim3(S_LEN, 5), 256>>>(qkv);
    // 3) causal flash attention (GQA; heads fastest, longest q-tiles first)
    flash_attn_h<<<dim3(NH, S_LEN / 128), 256, FA_SMEM>>>(qkv, ctx);
    // 4) output projection -> fp32 (single wave at 128x128)
    gemm_tn_h<128, false><<<dim3(CTX_N / 128, S_LEN / 128), 256, GEMM_SMEM_O>>>(ctx, wo16, out, S_LEN, CTX_N, CTX_N);
}

// round 14
// speedup vs baseline: 1.2720x; 1.0068x over previous
#include <cuda_runtime.h>
#include <cuda_fp16.h>
#include <math.h>
#include <stdint.h>

#define S_LEN 2048
#define HID   2048
#define NH    32
#define NKV   8
#define HD    64
#define QKV_N 3072
#define CTX_N 2048
#define K_OFF 2048
#define V_OFF 2560

// scratch (no cudaMalloc allowed)
__device__ __half g_h16 [S_LEN * HID];
__device__ __half g_wq16[QKV_N * HID];
__device__ __half g_wo16[HID * CTX_N];
__device__ __half g_qkv [S_LEN * QKV_N];
__device__ __half g_ctx [S_LEN * CTX_N];

// ---------------------------------------------------------------------------
__device__ __forceinline__ unsigned sptr(const void* p) {
    return (unsigned)__cvta_generic_to_shared(p);
}
#define CP_ASYNC16(dst, src) \
    asm volatile("cp.async.cg.shared.global [%0], [%1], 16;\n" :: "r"(dst), "l"(src))
#define CP_COMMIT() asm volatile("cp.async.commit_group;\n")
#define CP_WAIT0()  asm volatile("cp.async.wait_group 0;\n")
#define CP_WAIT1()  asm volatile("cp.async.wait_group 1;\n")
#define CP_WAIT2()  asm volatile("cp.async.wait_group 2;\n")

__device__ __forceinline__ void ldm_x4(unsigned& r0, unsigned& r1, unsigned& r2, unsigned& r3,
                                       unsigned addr) {
    asm volatile("ldmatrix.sync.aligned.m8n8.x4.shared.b16 {%0,%1,%2,%3}, [%4];\n"
                 : "=r"(r0), "=r"(r1), "=r"(r2), "=r"(r3) : "r"(addr));
}
__device__ __forceinline__ void ldm_x4t(unsigned& r0, unsigned& r1, unsigned& r2, unsigned& r3,
                                        unsigned addr) {
    asm volatile("ldmatrix.sync.aligned.m8n8.x4.trans.shared.b16 {%0,%1,%2,%3}, [%4];\n"
                 : "=r"(r0), "=r"(r1), "=r"(r2), "=r"(r3) : "r"(addr));
}
__device__ __forceinline__ void mma16816(float d[4], const unsigned a[4],
                                         unsigned b0, unsigned b1) {
    asm volatile("mma.sync.aligned.m16n8k16.row.col.f32.f16.f16.f32 "
                 "{%0,%1,%2,%3}, {%4,%5,%6,%7}, {%8,%9}, {%0,%1,%2,%3};\n"
                 : "+f"(d[0]), "+f"(d[1]), "+f"(d[2]), "+f"(d[3])
                 : "r"(a[0]), "r"(a[1]), "r"(a[2]), "r"(a[3]), "r"(b0), "r"(b1));
}
__device__ __forceinline__ unsigned packh2(float x, float y) {
    __half2 h = __floats2half2_rn(x, y);
    return *reinterpret_cast<unsigned*>(&h);
}
// fast exp2: single MUFU, guaranteed approx lowering regardless of compile flags
__device__ __forceinline__ float ex2(float x) {
    float r;
    asm("ex2.approx.ftz.f32 %0, %1;" : "=f"(r) : "f"(x));
    return r;
}

// ---------------------------------------------------------------------------
// fp32 -> fp16 conversion, 3 segments in one launch
// ---------------------------------------------------------------------------
#define F2H_L0 (S_LEN * HID / 4)
#define F2H_L1 (QKV_N * HID / 4)
#define F2H_L2 (HID * CTX_N / 4)
#define F2H_TOT (F2H_L0 + F2H_L1 + F2H_L2)

__global__ __launch_bounds__(256) void f2h3(const float4* __restrict__ s0, __half2* __restrict__ d0,
                                            const float4* __restrict__ s1, __half2* __restrict__ d1,
                                            const float4* __restrict__ s2, __half2* __restrict__ d2) {
    int i = blockIdx.x * 256 + threadIdx.x;
    const float4* s;
    __half2* d;
    if (i < F2H_L0) { s = s0; d = d0; }
    else if (i < F2H_L0 + F2H_L1) { i -= F2H_L0; s = s1; d = d1; }
    else if (i < F2H_TOT) { i -= F2H_L0 + F2H_L1; s = s2; d = d2; }
    else return;
    const float4 v = s[i];
    d[2 * i]     = __floats2half2_rn(v.x, v.y);
    d[2 * i + 1] = __floats2half2_rn(v.z, v.w);
}

// ---------------------------------------------------------------------------
// C[m][n] = sum_k A[m][k]*B[n][k], fp16 in / fp32 acc.  128 x NT x 64 tiles,
// 256 thr = 8 warps (2m x 4n, warp tile 64 x NT/4), 3-stage cp.async pipeline.
// smem per stage: A[128][64] + B[NT][64], row=128B, chunk swizzle c^(r&7).
// ---------------------------------------------------------------------------
template <int NT, bool HALF_OUT>
__global__ __launch_bounds__(256, 2) void gemm_tn_h(const __half* __restrict__ A,
                                                    const __half* __restrict__ B,
                                                    void* __restrict__ Cv,
                                                    int M, int N, int K) {
    constexpr int A_H = 128 * 64;          // A halves per stage
    constexpr int B_H = NT * 64;           // B halves per stage
    constexpr int STG = A_H + B_H;
    constexpr int NTL = NT / 32;           // n8-tiles per warp
    constexpr int NA = 4;                  // A 16B-chunk iters (1024/256)
    constexpr int NB = NT * 8 / 256;       // B 16B-chunk iters (exact)
    extern __shared__ __half gsm[];
    const int tid  = threadIdx.x;
    const int warp = tid >> 5, lane = tid & 31;
    const int gid  = lane >> 2, tg = lane & 3;
    const int wm   = warp & 1,  wn = warp >> 1;
    const int m0 = blockIdx.y * 128, n0 = blockIdx.x * NT;

    int swa[NA]; long ga[NA];
#pragma unroll
    for (int i = 0; i < NA; i++) {
        const int f = tid + i * 256, r = f >> 3, c = f & 7;
        swa[i] = r * 64 + ((c ^ (r & 7)) << 3);
        ga[i]  = (long)(m0 + r) * K + c * 8;
    }
    int swb[NB]; long gb[NB];
#pragma unroll
    for (int i = 0; i < NB; i++) {
        const int f = tid + i * 256, r = f >> 3, c = f & 7;
        swb[i] = r * 64 + ((c ^ (r & 7)) << 3);
        gb[i]  = (long)(n0 + r) * K + c * 8;
    }

    float acc[4][NTL][4] = {};

#define G_LOAD(IT)                                                      \
    do {                                                                \
        const int kk_ = (IT) << 6;                                      \
        __half* a_ = gsm + ((IT) % 3) * STG;                            \
        __half* b_ = a_ + A_H;                                          \
        _Pragma("unroll")                                               \
        for (int i_ = 0; i_ < NA; i_++)                                 \
            CP_ASYNC16(sptr(a_ + swa[i_]), A + ga[i_] + kk_);           \
        _Pragma("unroll")                                               \
        for (int i_ = 0; i_ < NB; i_++)                                 \
            CP_ASYNC16(sptr(b_ + swb[i_]), B + gb[i_] + kk_);           \
        CP_COMMIT();                                                    \
    } while (0)

    const int nIter = K >> 6;
    G_LOAD(0); G_LOAD(1);

    for (int it = 0; it < nIter; ++it) {
        if (it + 1 < nIter) { CP_WAIT1(); } else { CP_WAIT0(); }
        __syncthreads();
        if (it + 2 < nIter) G_LOAD(it + 2);

        const __half* a = gsm + (it % 3) * STG;
        const __half* b = a + A_H;

#pragma unroll
        for (int half = 0; half < 2; half++) {
            unsigned bf[NTL][4];
            {
                const int rb = wn * (NT / 4) + (lane & 7);
                const int cb = 4 * half + (lane >> 3);
#pragma unroll
                for (int nt = 0; nt < NTL; nt++) {
                    const int r = rb + nt * 8;
                    ldm_x4(bf[nt][0], bf[nt][1], bf[nt][2], bf[nt][3],
                           sptr(b + r * 64 + ((cb ^ (r & 7)) << 3)));
                }
            }
#pragma unroll
            for (int p2 = 0; p2 < 2; p2++) {
                const int p = 2 * half + p2;
                unsigned af[4][4];
                const int ra = wm * 64 + (lane & 7) + ((lane >> 3) & 1) * 8;
                const int ca = p * 2 + ((lane >> 4) & 1);
#pragma unroll
                for (int mt = 0; mt < 4; mt++) {
                    const int r = ra + mt * 16;
                    ldm_x4(af[mt][0], af[mt][1], af[mt][2], af[mt][3],
                           sptr(a + r * 64 + ((ca ^ (r & 7)) << 3)));
                }
#pragma unroll
                for (int nt = 0; nt < NTL; nt++)
#pragma unroll
                    for (int mt = 0; mt < 4; mt++)
                        mma16816(acc[mt][nt], af[mt], bf[nt][2 * p2], bf[nt][2 * p2 + 1]);
            }
        }
    }

#pragma unroll
    for (int mt = 0; mt < 4; mt++)
#pragma unroll
        for (int nt = 0; nt < NTL; nt++) {
            const int r = m0 + wm * 64 + mt * 16 + gid;
            const int c = n0 + wn * (NT / 4) + nt * 8 + tg * 2;
            if (HALF_OUT) {
                __half* C = (__half*)Cv;
                *(__half2*)&C[(long)r * N + c] =
                    __floats2half2_rn(acc[mt][nt][0], acc[mt][nt][1]);
                *(__half2*)&C[(long)(r + 8) * N + c] =
                    __floats2half2_rn(acc[mt][nt][2], acc[mt][nt][3]);
            } else {
                float* C = (float*)Cv;
                *(float2*)&C[(long)r * N + c] = make_float2(acc[mt][nt][0], acc[mt][nt][1]);
                *(float2*)&C[(long)(r + 8) * N + c] = make_float2(acc[mt][nt][2], acc[mt][nt][3]);
            }
        }
}

#define GEMM_SMEM_Q (3 * (128 + 96) * 64 * 2)    // NT=96  -> 86016 B
#define GEMM_SMEM_O (3 * (128 + 128) * 64 * 2)   // NT=128 -> 98304 B

// ---------------------------------------------------------------------------
// RoPE (neox) in-place on fp16 q,k.  positions = arange(S).
// Folds 0.125 * log2(e) into q (FA softmax runs in exp2 domain).
// 256 threads = 8 heads per block.
// ---------------------------------------------------------------------------
__global__ __launch_bounds__(256) void rope_h(__half* __restrict__ qkv) {
    const int s  = blockIdx.x;
    const int hh = blockIdx.y * 8 + (threadIdx.x >> 5);
    const int i  = threadIdx.x & 31;
    const int base = (hh < NH) ? hh * HD : (K_OFF + (hh - NH) * HD);
    const float qs = (hh < NH) ? 0.125f * 1.44269504f : 1.0f;
    const float inv = powf(10000.0f, -(2.0f * (float)i) / 64.0f);
    const float ang = (float)s * inv;
    const float c = cosf(ang), sn = sinf(ang);
    __half* row = qkv + (long)s * QKV_N + base;
    const float x1 = __half2float(row[i]);
    const float x2 = __half2float(row[i + 32]);
    row[i]      = __float2half_rn((x1 * c - x2 * sn) * qs);
    row[i + 32] = __float2half_rn((x2 * c + x1 * sn) * qs);
}

// ---------------------------------------------------------------------------
// Causal flash attention, fp16 mma.  128 q-rows/block, 8 warps (16 rows each),
// 3-stage K/V cp.async pipeline, V via ldmatrix.x4.trans, P stays in regs.
// Stale-max online softmax; exp via ex2.approx; acc-rescale skipped via warp
// vote when the running max did not grow.  Row sums via all-ones MMA.
// ---------------------------------------------------------------------------
#define FQ_H (128 * 64)
#define FKV_H (64 * 64)
#define FA_SMEM ((FQ_H + 3 * 2 * FKV_H) * 2)
#define ONES_H2 0x3C003C00u

__global__ __launch_bounds__(256, 2) void flash_attn_h(const __half* __restrict__ qkv,
                                                       __half* __restrict__ ctx) {
    extern __shared__ __half fsm[];
    __half* Qs = fsm;   // [128][64]

    const int qt  = (S_LEN / 128 - 1) - blockIdx.y;   // longest tiles first, heads fastest
    const int h   = blockIdx.x;
    const int kvh = h >> 2;
    const int tid = threadIdx.x, warp = tid >> 5, lane = tid & 31;
    const int gid = lane >> 2, tg = lane & 3;
    const int q0 = qt * 128, woff = warp * 16;
    const int jmax = (q0 + 127) >> 6;

    int rr[2], cc8[2], sw[2];
#pragma unroll
    for (int i = 0; i < 2; i++) {
        const int f = tid + i * 256;
        const int r = f >> 3, c = f & 7;
        rr[i] = r; cc8[i] = c * 8;
        sw[i] = r * 64 + ((c ^ (r & 7)) << 3);
    }

#define FA_LOADKV(J)                                                                     \
    do {                                                                                 \
        const int kb_ = (J) * 64;                                                        \
        __half* kd_ = fsm + FQ_H + ((J) % 3) * 2 * FKV_H;                                \
        __half* vd_ = kd_ + FKV_H;                                                       \
        _Pragma("unroll")                                                                \
        for (int i_ = 0; i_ < 2; i_++) {                                                 \
            CP_ASYNC16(sptr(kd_ + sw[i_]),                                               \
                       qkv + (long)(kb_ + rr[i_]) * QKV_N + K_OFF + kvh * HD + cc8[i_]); \
            CP_ASYNC16(sptr(vd_ + sw[i_]),                                               \
                       qkv + (long)(kb_ + rr[i_]) * QKV_N + V_OFF + kvh * HD + cc8[i_]); \
        }                                                                                \
        CP_COMMIT();                                                                     \
    } while (0)

    // prologue: Q (1024 chunks, 4/thread) then KV0, KV1
#pragma unroll
    for (int i = 0; i < 4; i++) {
        const int f = tid + i * 256;
        const int r = f >> 3, c = f & 7;
        CP_ASYNC16(sptr(Qs + r * 64 + ((c ^ (r & 7)) << 3)),
                   qkv + (long)(q0 + r) * QKV_N + h * HD + c * 8);
    }
    CP_COMMIT();
    FA_LOADKV(0);
    FA_LOADKV(1);

    CP_WAIT2();          // Q done (KV0, KV1 may be in flight)
    __syncthreads();

    unsigned qa[4][4];
    {
        const int r = woff + (lane & 7) + ((lane >> 3) & 1) * 8;
        const int cb = (lane >> 4) & 1;
#pragma unroll
        for (int ks = 0; ks < 4; ks++) {
            const int c = 2 * ks + cb;
            ldm_x4(qa[ks][0], qa[ks][1], qa[ks][2], qa[ks][3],
                   sptr(Qs + r * 64 + ((c ^ (r & 7)) << 3)));
        }
    }

    float acc[8][4] = {};
    float lsum[4] = {};
    float b0 = 0.0f, b1 = 0.0f;     // current exp basis
    float al0 = 1.0f, al1 = 1.0f;   // rescale factor pending for next iter
    bool first = true;

    for (int j = 0; j <= jmax; ++j) {
        if (j < jmax) { CP_WAIT1(); } else { CP_WAIT0(); }
        __syncthreads();
        if (j + 2 <= jmax) FA_LOADKV(j + 2);

        // skip fully-masked iterations for this warp (still did sync+prefetch)
        if ((j << 6) > q0 + woff + 15) continue;

        const __half* ksm = fsm + FQ_H + (j % 3) * 2 * FKV_H;
        const __half* vsm = ksm + FKV_H;

        // ---- S = Q K^T ----
        float sf[8][4] = {};
#pragma unroll
        for (int p = 0; p < 2; p++) {
            const int rb = lane & 7;
            const int cb = 4 * p + (lane >> 3);
#pragma unroll
            for (int nt = 0; nt < 8; nt++) {
                unsigned kb[4];
                const int r = nt * 8 + rb;
                ldm_x4(kb[0], kb[1], kb[2], kb[3],
                       sptr(ksm + r * 64 + ((cb ^ (r & 7)) << 3)));
                mma16816(sf[nt], qa[2 * p],     kb[0], kb[1]);
                mma16816(sf[nt], qa[2 * p + 1], kb[2], kb[3]);
            }
        }

        // ---- causal mask (absolute coords; only near diagonal) ----
        if ((j << 6) + 63 > q0 + woff) {
            const int r0m = q0 + woff + gid;
            const int r1m = r0m + 8;
#pragma unroll
            for (int nt = 0; nt < 8; nt++) {
                const int c0 = (j << 6) + nt * 8 + tg * 2;
                if (c0 > r0m)     sf[nt][0] = -INFINITY;
                if (c0 + 1 > r0m) sf[nt][1] = -INFINITY;
                if (c0 > r1m)     sf[nt][2] = -INFINITY;
                if (c0 + 1 > r1m) sf[nt][3] = -INFINITY;
            }
        }

        // ---- local (per-thread) row max of raw scores ----
        float mx0 = sf[0][0], mx1 = sf[0][2];
#pragma unroll
        for (int nt = 0; nt < 8; nt++) {
            mx0 = fmaxf(mx0, fmaxf(sf[nt][0], sf[nt][1]));
            mx1 = fmaxf(mx1, fmaxf(sf[nt][2], sf[nt][3]));
        }

        if (first) {
            // exact path once per warp: reduce max across quad before exp
            mx0 = fmaxf(mx0, __shfl_xor_sync(0xffffffffu, mx0, 1));
            mx0 = fmaxf(mx0, __shfl_xor_sync(0xffffffffu, mx0, 2));
            mx1 = fmaxf(mx1, __shfl_xor_sync(0xffffffffu, mx1, 1));
            mx1 = fmaxf(mx1, __shfl_xor_sync(0xffffffffu, mx1, 2));
            b0 = mx0; b1 = mx1;
            first = false;
        } else {
            // apply rescale factor only when the max actually grew (warp vote)
            if (__any_sync(0xffffffffu, (al0 < 1.0f) || (al1 < 1.0f))) {
#pragma unroll
                for (int dt = 0; dt < 8; dt++) {
                    acc[dt][0] *= al0; acc[dt][1] *= al0;
                    acc[dt][2] *= al1; acc[dt][3] *= al1;
                }
                lsum[0] *= al0; lsum[1] *= al0;
                lsum[2] *= al1; lsum[3] *= al1;
            }
        }

        // ---- exp with (possibly stale) basis b (ex2.approx) ----
#pragma unroll
        for (int nt = 0; nt < 8; nt++) {
            sf[nt][0] = ex2(sf[nt][0] - b0);
            sf[nt][1] = ex2(sf[nt][1] - b0);
            sf[nt][2] = ex2(sf[nt][2] - b1);
            sf[nt][3] = ex2(sf[nt][3] - b1);
        }

        // ---- P: C-frag -> A-frag repack (registers only) ----
        unsigned pa[4][4];
#pragma unroll
        for (int ks = 0; ks < 4; ks++) {
            pa[ks][0] = packh2(sf[2 * ks][0],     sf[2 * ks][1]);
            pa[ks][1] = packh2(sf[2 * ks][2],     sf[2 * ks][3]);
            pa[ks][2] = packh2(sf[2 * ks + 1][0], sf[2 * ks + 1][1]);
            pa[ks][3] = packh2(sf[2 * ks + 1][2], sf[2 * ks + 1][3]);
        }

        // ---- O += P V  (V via ldmatrix.trans); row sums via ones-MMA ----
#pragma unroll
        for (int p = 0; p < 2; p++) {
            const int r = 32 * p + (lane & 7) + (lane >> 3) * 8;
#pragma unroll
            for (int dt = 0; dt < 8; dt++) {
                unsigned vb[4];
                ldm_x4t(vb[0], vb[1], vb[2], vb[3],
                        sptr(vsm + r * 64 + ((dt ^ (r & 7)) << 3)));
                mma16816(acc[dt], pa[2 * p],     vb[0], vb[1]);
                mma16816(acc[dt], pa[2 * p + 1], vb[2], vb[3]);
            }
            mma16816(lsum, pa[2 * p],     ONES_H2, ONES_H2);
            mma16816(lsum, pa[2 * p + 1], ONES_H2, ONES_H2);
        }

        // ---- deferred max update (runs in the MMA shadow) ----
        mx0 = fmaxf(mx0, __shfl_xor_sync(0xffffffffu, mx0, 1));
        mx0 = fmaxf(mx0, __shfl_xor_sync(0xffffffffu, mx0, 2));
        mx1 = fmaxf(mx1, __shfl_xor_sync(0xffffffffu, mx1, 1));
        mx1 = fmaxf(mx1, __shfl_xor_sync(0xffffffffu, mx1, 2));
        const float bn0 = fmaxf(b0, mx0);
        const float bn1 = fmaxf(b1, mx1);
        al0 = ex2(b0 - bn0);
        al1 = ex2(b1 - bn1);
        b0 = bn0; b1 = bn1;
    }

    // ---- epilogue (basis cancels in O/l) ----
    const float il0 = 1.0f / lsum[0];
    const float il1 = 1.0f / lsum[2];
#pragma unroll
    for (int dt = 0; dt < 8; dt++) {
        const int r = q0 + woff + gid;
        const int c = h * HD + dt * 8 + tg * 2;
        *(__half2*)&ctx[(long)r * CTX_N + c] =
            __floats2half2_rn(acc[dt][0] * il0, acc[dt][1] * il0);
        *(__half2*)&ctx[(long)(r + 8) * CTX_N + c] =
            __floats2half2_rn(acc[dt][2] * il1, acc[dt][3] * il1);
    }
}

// ---------------------------------------------------------------------------
extern "C" void kernel_launch(void* const* d_in, const int* in_sizes, int n_in,
                              void* d_out, int out_size) {
    const float* hidden = (const float*)d_in[1];
    const float* w_qkv  = (const float*)d_in[2];
    const float* w_o    = (const float*)d_in[3];
    float* out = (float*)d_out;

    __half *h16, *wq16, *wo16, *qkv, *ctx;
    cudaGetSymbolAddress((void**)&h16,  g_h16);
    cudaGetSymbolAddress((void**)&wq16, g_wq16);
    cudaGetSymbolAddress((void**)&wo16, g_wo16);
    cudaGetSymbolAddress((void**)&qkv,  g_qkv);
    cudaGetSymbolAddress((void**)&ctx,  g_ctx);

    cudaFuncSetAttribute(gemm_tn_h<96, true>,   cudaFuncAttributeMaxDynamicSharedMemorySize, GEMM_SMEM_Q);
    cudaFuncSetAttribute(gemm_tn_h<128, false>, cudaFuncAttributeMaxDynamicSharedMemorySize, GEMM_SMEM_O);
    cudaFuncSetAttribute(flash_attn_h,          cudaFuncAttributeMaxDynamicSharedMemorySize, FA_SMEM);

    // 0) fp32 -> fp16 conversions (single launch, 3 segments)
    f2h3<<<(F2H_TOT + 255) / 256, 256>>>((const float4*)hidden, (__half2*)h16,
                                         (const float4*)w_qkv, (__half2*)wq16,
                                         (const float4*)w_o,   (__half2*)wo16);

    // 1) fused QKV projection -> fp16 (128x96x64 tiles, 3-stage)
    gemm_tn_h<96, true><<<dim3(QKV_N / 96, S_LEN / 128), 256, GEMM_SMEM_Q>>>(h16, wq16, qkv, S_LEN, QKV_N, HID);
    // 2) RoPE (0.125*log2e folded into q)
    rope_h<<<dim3(S_LEN, 5), 256>>>(qkv);
    // 3) causal flash attention (GQA; heads fastest, longest q-tiles first)
    flash_attn_h<<<dim3(NH, S_LEN / 128), 256, FA_SMEM>>>(qkv, ctx);
    // 4) output projection -> fp32 (128x128x64 tiles, 3-stage, single wave)
    gemm_tn_h<128, false><<<dim3(CTX_N / 128, S_LEN / 128), 256, GEMM_SMEM_O>>>(ctx, wo16, out, S_LEN, CTX_N, CTX_N);
}